// round 2
// baseline (speedup 1.0000x reference)
#include <cuda_runtime.h>
#include <math.h>

#define B_DIM 4
#define T_DIM 4096
#define C_DIM 1024
#define H_DIM 64

// Scratch for Q, K, V projections (no cudaMalloc allowed -> device globals).
__device__ float g_Q[B_DIM * T_DIM * H_DIM];
__device__ float g_K[B_DIM * T_DIM * H_DIM];
__device__ float g_V[B_DIM * T_DIM * H_DIM];

// ---------------------------------------------------------------------------
// QKV projection: Out[row, n] = sum_k x[row, k] * W[k, n]
// x viewed as [B*T, C]. Grid: (rows/64, 3). Block 256 threads, 64x64 tile,
// 4x4 per-thread register tile, k-chunks of 32.
// ---------------------------------------------------------------------------
__global__ __launch_bounds__(256) void qkv_proj_kernel(
    const float* __restrict__ x,
    const float* __restrict__ Wq,
    const float* __restrict__ Wk,
    const float* __restrict__ Wv)
{
    __shared__ float Xst[32][68];  // [k][row] (transposed for LDS.128)
    __shared__ float Ws[32][68];   // [k][n]   (natural W layout)

    const float* W;
    float* Out;
    if (blockIdx.y == 0)      { W = Wq; Out = g_Q; }
    else if (blockIdx.y == 1) { W = Wk; Out = g_K; }
    else                      { W = Wv; Out = g_V; }

    const int row0 = blockIdx.x * 64;
    const int tid  = threadIdx.x;
    const int r    = tid >> 4;   // 0..15 -> rows 4r..4r+3
    const int c    = tid & 15;   // 0..15 -> cols 4c..4c+3

    float acc[4][4];
#pragma unroll
    for (int i = 0; i < 4; i++)
#pragma unroll
        for (int j = 0; j < 4; j++) acc[i][j] = 0.f;

    for (int k0 = 0; k0 < C_DIM; k0 += 32) {
        // Load 64x32 slice of x, transposed into smem.
#pragma unroll
        for (int it = 0; it < 8; it++) {
            int idx = tid + it * 256;
            int row = idx >> 5;
            int k   = idx & 31;
            Xst[k][row] = x[(size_t)(row0 + row) * C_DIM + k0 + k];
        }
        // Load 32x64 slice of W (already [k][n]).
#pragma unroll
        for (int it = 0; it < 8; it++) {
            int idx = tid + it * 256;
            int k   = idx >> 6;
            int n   = idx & 63;
            Ws[k][n] = W[(size_t)(k0 + k) * H_DIM + n];
        }
        __syncthreads();

#pragma unroll 8
        for (int k = 0; k < 32; k++) {
            float4 a = *(const float4*)&Xst[k][4 * r];
            float4 b = *(const float4*)&Ws[k][4 * c];
            float av[4] = {a.x, a.y, a.z, a.w};
            float bv[4] = {b.x, b.y, b.z, b.w};
#pragma unroll
            for (int i = 0; i < 4; i++)
#pragma unroll
                for (int j = 0; j < 4; j++)
                    acc[i][j] = fmaf(av[i], bv[j], acc[i][j]);
        }
        __syncthreads();
    }

#pragma unroll
    for (int i = 0; i < 4; i++)
#pragma unroll
        for (int j = 0; j < 4; j++)
            Out[(size_t)(row0 + 4 * r + i) * H_DIM + 4 * c + j] = acc[i][j];
}

// ---------------------------------------------------------------------------
// Flash attention (causal, single head).
// Grid: (T/64 q-tiles, B). Block 256 threads.
// smem (dynamic, ~68KB): Qs,Ks [k][row] transposed; Vs [kv][d]; Ps [row][col].
// ---------------------------------------------------------------------------
#define SM_STRIDE 68
#define TILE_ELEMS (64 * SM_STRIDE)

__global__ __launch_bounds__(256) void attn_kernel(float* __restrict__ out)
{
    extern __shared__ float sm[];
    float* Qs = sm;                   // [k][row], stride 68
    float* Ks = sm + TILE_ELEMS;      // [k][col], stride 68
    float* Vs = sm + 2 * TILE_ELEMS;  // [kv][d],  stride 68
    float* Ps = sm + 3 * TILE_ELEMS;  // [row][col], stride 68

    const int qt = blockIdx.x;
    const int b  = blockIdx.y;
    const int q0 = qt * 64;

    const float* Q = g_Q + (size_t)b * T_DIM * H_DIM;
    const float* K = g_K + (size_t)b * T_DIM * H_DIM;
    const float* V = g_V + (size_t)b * T_DIM * H_DIM;

    const int tid = threadIdx.x;
    const int r   = tid >> 4;  // rows 4r..4r+3
    const int c   = tid & 15;  // cols 4c..4c+3

    // Load Q tile transposed: Qs[k][row]
#pragma unroll
    for (int it = 0; it < 16; it++) {
        int idx = tid + it * 256;
        int row = idx >> 6;
        int k   = idx & 63;
        Qs[k * SM_STRIDE + row] = Q[(size_t)(q0 + row) * H_DIM + k];
    }

    float m[4], l[4], acc[4][4];
#pragma unroll
    for (int i = 0; i < 4; i++) {
        m[i] = -1e30f;
        l[i] = 0.f;
#pragma unroll
        for (int j = 0; j < 4; j++) acc[i][j] = 0.f;
    }

    const float scale = 0.03125f;  // 1/sqrt(1024)

    for (int kt = 0; kt <= qt; kt++) {
        const int kv0 = kt * 64;
        __syncthreads();  // previous iter's Ks/Vs/Ps reads done (also Qs 1st iter)
        // Load K (transposed) and V (natural) tiles.
#pragma unroll
        for (int it = 0; it < 16; it++) {
            int idx = tid + it * 256;
            int row = idx >> 6;
            int k   = idx & 63;
            float kv = K[(size_t)(kv0 + row) * H_DIM + k];
            float vv = V[(size_t)(kv0 + row) * H_DIM + k];
            Ks[k * SM_STRIDE + row]   = kv;
            Vs[row * SM_STRIDE + k]   = vv;
        }
        __syncthreads();

        // S = Q K^T  (per-thread 4x4)
        float s[4][4];
#pragma unroll
        for (int i = 0; i < 4; i++)
#pragma unroll
            for (int j = 0; j < 4; j++) s[i][j] = 0.f;

#pragma unroll 8
        for (int k = 0; k < 64; k++) {
            float4 a = *(const float4*)&Qs[k * SM_STRIDE + 4 * r];
            float4 bb = *(const float4*)&Ks[k * SM_STRIDE + 4 * c];
            float av[4] = {a.x, a.y, a.z, a.w};
            float bv[4] = {bb.x, bb.y, bb.z, bb.w};
#pragma unroll
            for (int i = 0; i < 4; i++)
#pragma unroll
                for (int j = 0; j < 4; j++)
                    s[i][j] = fmaf(av[i], bv[j], s[i][j]);
        }

        // Scale + causal mask (only the diagonal tile can mask).
        const bool diag = (kt == qt);
#pragma unroll
        for (int i = 0; i < 4; i++) {
            int qg = q0 + 4 * r + i;
#pragma unroll
            for (int j = 0; j < 4; j++) {
                float v = s[i][j] * scale;
                if (diag && (kv0 + 4 * c + j > qg)) v = -1e30f;
                s[i][j] = v;
            }
        }

        // Online softmax per row (reduce across the 16 threads of a row group).
#pragma unroll
        for (int i = 0; i < 4; i++) {
            float mt = fmaxf(fmaxf(s[i][0], s[i][1]), fmaxf(s[i][2], s[i][3]));
#pragma unroll
            for (int w = 8; w >= 1; w >>= 1)
                mt = fmaxf(mt, __shfl_xor_sync(0xffffffffu, mt, w));
            float mn = fmaxf(m[i], mt);
            float alpha = __expf(m[i] - mn);
            float sum = 0.f;
#pragma unroll
            for (int j = 0; j < 4; j++) {
                float p = __expf(s[i][j] - mn);
                s[i][j] = p;
                sum += p;
            }
#pragma unroll
            for (int w = 8; w >= 1; w >>= 1)
                sum += __shfl_xor_sync(0xffffffffu, sum, w);
            l[i] = l[i] * alpha + sum;
            m[i] = mn;
#pragma unroll
            for (int j = 0; j < 4; j++) acc[i][j] *= alpha;
            // Stash P tile
#pragma unroll
            for (int j = 0; j < 4; j++)
                Ps[(4 * r + i) * SM_STRIDE + 4 * c + j] = s[i][j];
        }
        __syncthreads();

        // O += P @ V  (per-thread 4 rows x 4 d-cols)
#pragma unroll 8
        for (int k = 0; k < 64; k++) {
            float4 v = *(const float4*)&Vs[k * SM_STRIDE + 4 * c];
            float vv[4] = {v.x, v.y, v.z, v.w};
            float p0 = Ps[(4 * r + 0) * SM_STRIDE + k];
            float p1 = Ps[(4 * r + 1) * SM_STRIDE + k];
            float p2 = Ps[(4 * r + 2) * SM_STRIDE + k];
            float p3 = Ps[(4 * r + 3) * SM_STRIDE + k];
#pragma unroll
            for (int j = 0; j < 4; j++) {
                acc[0][j] = fmaf(p0, vv[j], acc[0][j]);
                acc[1][j] = fmaf(p1, vv[j], acc[1][j]);
                acc[2][j] = fmaf(p2, vv[j], acc[2][j]);
                acc[3][j] = fmaf(p3, vv[j], acc[3][j]);
            }
        }
    }

    // Epilogue: normalize and write out.
#pragma unroll
    for (int i = 0; i < 4; i++) {
        float inv_l = 1.f / l[i];
#pragma unroll
        for (int j = 0; j < 4; j++)
            out[((size_t)b * T_DIM + q0 + 4 * r + i) * H_DIM + 4 * c + j] =
                acc[i][j] * inv_l;
    }
}

// ---------------------------------------------------------------------------
extern "C" void kernel_launch(void* const* d_in, const int* in_sizes, int n_in,
                              void* d_out, int out_size)
{
    (void)in_sizes; (void)n_in; (void)out_size;
    const float* x  = (const float*)d_in[0];
    const float* Wq = (const float*)d_in[1];
    const float* Wk = (const float*)d_in[2];
    const float* Wv = (const float*)d_in[3];
    float* out = (float*)d_out;

    // QKV projection: (B*T)/64 row tiles x 3 matrices.
    dim3 gproj((B_DIM * T_DIM) / 64, 3);
    qkv_proj_kernel<<<gproj, 256>>>(x, Wq, Wk, Wv);

    // Flash attention: opt into >48KB dynamic smem (idempotent, capture-safe).
    const int smem_bytes = 4 * TILE_ELEMS * (int)sizeof(float);  // 69632
    cudaFuncSetAttribute(attn_kernel,
                         cudaFuncAttributeMaxDynamicSharedMemorySize, smem_bytes);
    dim3 gattn(T_DIM / 64, B_DIM);
    attn_kernel<<<gattn, 256, smem_bytes>>>(out);
}

// round 3
// speedup vs baseline: 1.3004x; 1.3004x over previous
#include <cuda_runtime.h>
#include <stdint.h>
#include <math.h>

#define B_DIM 4
#define T_DIM 4096
#define C_DIM 1024
#define H_DIM 64

// Scratch for Q, K, V projections (no cudaMalloc allowed -> device globals).
__device__ float g_Q[B_DIM * T_DIM * H_DIM];
__device__ float g_K[B_DIM * T_DIM * H_DIM];
__device__ float g_V[B_DIM * T_DIM * H_DIM];

// ---------------- packed f32x2 helpers (FFMA2 is PTX-only) ------------------
__device__ __forceinline__ uint64_t pack2(float x, float y) {
    uint64_t r;
    asm("mov.b64 %0, {%1, %2};" : "=l"(r) : "f"(x), "f"(y));
    return r;
}
__device__ __forceinline__ uint64_t bcast2(float x) { return pack2(x, x); }
__device__ __forceinline__ void ffma2(uint64_t& d, uint64_t a, uint64_t b) {
    asm("fma.rn.f32x2 %0, %1, %2, %0;" : "+l"(d) : "l"(a), "l"(b));
}
__device__ __forceinline__ void mul2(uint64_t& d, uint64_t a) {
    asm("mul.rn.f32x2 %0, %0, %1;" : "+l"(d) : "l"(a));
}
__device__ __forceinline__ float2 unpack2(uint64_t v) {
    float2 f;
    asm("mov.b64 {%0, %1}, %2;" : "=f"(f.x), "=f"(f.y) : "l"(v));
    return f;
}

// ---------------------------------------------------------------------------
// Fused QKV projection: reads each x tile ONCE, produces Q,K,V 64-col tiles.
// Grid: (B*T)/64. Block 256. Per-thread 4 rows x (3 mats x 4 cols), packed.
// ---------------------------------------------------------------------------
__global__ __launch_bounds__(256) void qkv_proj_kernel(
    const float* __restrict__ x,
    const float* __restrict__ Wq,
    const float* __restrict__ Wk,
    const float* __restrict__ Wv)
{
    __shared__ float Xst[32][68];     // [k][row] transposed
    __shared__ float Ws[3][32][68];   // [mat][k][n]

    const float* Wm[3] = {Wq, Wk, Wv};

    const int row0 = blockIdx.x * 64;
    const int tid  = threadIdx.x;
    const int r    = tid >> 4;   // rows 4r..4r+3
    const int c    = tid & 15;   // cols 4c..4c+3 (per matrix)

    uint64_t acc[4][3][2];
#pragma unroll
    for (int i = 0; i < 4; i++)
#pragma unroll
        for (int m = 0; m < 3; m++) { acc[i][m][0] = 0ull; acc[i][m][1] = 0ull; }

    for (int k0 = 0; k0 < C_DIM; k0 += 32) {
        // x tile 64x32, vectorized loads, transposed stores.
#pragma unroll
        for (int it = 0; it < 2; it++) {
            int v   = tid + it * 256;
            int row = v >> 3;
            int kq  = (v & 7) * 4;
            float4 xx = *(const float4*)&x[(size_t)(row0 + row) * C_DIM + k0 + kq];
            Xst[kq + 0][row] = xx.x;
            Xst[kq + 1][row] = xx.y;
            Xst[kq + 2][row] = xx.z;
            Xst[kq + 3][row] = xx.w;
        }
        // W tiles 32x64 each, natural layout, vector stores.
#pragma unroll
        for (int m = 0; m < 3; m++) {
#pragma unroll
            for (int it = 0; it < 2; it++) {
                int v  = tid + it * 256;
                int kk = v >> 4;
                int n  = (v & 15) * 4;
                *(float4*)&Ws[m][kk][n] =
                    *(const float4*)&Wm[m][(size_t)(k0 + kk) * H_DIM + n];
            }
        }
        __syncthreads();

#pragma unroll 8
        for (int k = 0; k < 32; k++) {
            float4 a = *(const float4*)&Xst[k][4 * r];
            uint64_t pa[4] = {bcast2(a.x), bcast2(a.y), bcast2(a.z), bcast2(a.w)};
#pragma unroll
            for (int m = 0; m < 3; m++) {
                float4 b = *(const float4*)&Ws[m][k][4 * c];
                uint64_t b0 = pack2(b.x, b.y);
                uint64_t b1 = pack2(b.z, b.w);
#pragma unroll
                for (int i = 0; i < 4; i++) {
                    ffma2(acc[i][m][0], pa[i], b0);
                    ffma2(acc[i][m][1], pa[i], b1);
                }
            }
        }
        __syncthreads();
    }

    float* Om[3] = {g_Q, g_K, g_V};
#pragma unroll
    for (int m = 0; m < 3; m++)
#pragma unroll
        for (int i = 0; i < 4; i++) {
            float2 lo = unpack2(acc[i][m][0]);
            float2 hi = unpack2(acc[i][m][1]);
            *(float4*)&Om[m][(size_t)(row0 + 4 * r + i) * H_DIM + 4 * c] =
                make_float4(lo.x, lo.y, hi.x, hi.y);
        }
}

// ---------------------------------------------------------------------------
// Flash attention (causal). Grid: 256 (qt descending, batch-interleaved).
// Block 256. Packed f32x2 FMA in both matmul loops.
// ---------------------------------------------------------------------------
#define SM_STRIDE 68
#define TILE_ELEMS (64 * SM_STRIDE)

__global__ __launch_bounds__(256) void attn_kernel(float* __restrict__ out)
{
    extern __shared__ float sm[];
    float* Qs = sm;                   // [k][row]
    float* Ks = sm + TILE_ELEMS;      // [k][col]
    float* Vs = sm + 2 * TILE_ELEMS;  // [kv][d]
    float* Ps = sm + 3 * TILE_ELEMS;  // [row][col]

    // Work ordering: heaviest q-tiles first, interleaved across batches.
    const int g  = blockIdx.x;
    const int qt = (T_DIM / 64 - 1) - (g >> 2);
    const int b  = g & 3;
    const int q0 = qt * 64;

    const float* Q = g_Q + (size_t)b * T_DIM * H_DIM;
    const float* K = g_K + (size_t)b * T_DIM * H_DIM;
    const float* V = g_V + (size_t)b * T_DIM * H_DIM;

    const int tid = threadIdx.x;
    const int r   = tid >> 4;
    const int c   = tid & 15;

    // Load Q tile (vectorized along d, transposed store).
#pragma unroll
    for (int it = 0; it < 4; it++) {
        int v   = tid + it * 256;
        int row = v >> 4;
        int kq  = (v & 15) * 4;
        float4 qq = *(const float4*)&Q[(size_t)(q0 + row) * H_DIM + kq];
        Qs[(kq + 0) * SM_STRIDE + row] = qq.x;
        Qs[(kq + 1) * SM_STRIDE + row] = qq.y;
        Qs[(kq + 2) * SM_STRIDE + row] = qq.z;
        Qs[(kq + 3) * SM_STRIDE + row] = qq.w;
    }

    float m[4], l[4];
    uint64_t o2[4][2];
#pragma unroll
    for (int i = 0; i < 4; i++) {
        m[i] = -1e30f;
        l[i] = 0.f;
        o2[i][0] = 0ull;
        o2[i][1] = 0ull;
    }

    const float scale = 0.03125f;  // 1/sqrt(1024)

    for (int kt = 0; kt <= qt; kt++) {
        const int kv0 = kt * 64;
        __syncthreads();  // prior reads of Ks/Vs/Ps complete (covers Qs 1st iter)

        // Load K (transposed) and V (natural), vectorized along d.
#pragma unroll
        for (int it = 0; it < 4; it++) {
            int v   = tid + it * 256;
            int row = v >> 4;
            int kq  = (v & 15) * 4;
            float4 kk = *(const float4*)&K[(size_t)(kv0 + row) * H_DIM + kq];
            Ks[(kq + 0) * SM_STRIDE + row] = kk.x;
            Ks[(kq + 1) * SM_STRIDE + row] = kk.y;
            Ks[(kq + 2) * SM_STRIDE + row] = kk.z;
            Ks[(kq + 3) * SM_STRIDE + row] = kk.w;
            float4 vv = *(const float4*)&V[(size_t)(kv0 + row) * H_DIM + kq];
            *(float4*)&Vs[row * SM_STRIDE + kq] = vv;
        }
        __syncthreads();

        // S = Q K^T (packed: 8 FFMA2 per k per thread)
        uint64_t s2[4][2];
#pragma unroll
        for (int i = 0; i < 4; i++) { s2[i][0] = 0ull; s2[i][1] = 0ull; }

#pragma unroll 8
        for (int k = 0; k < 64; k++) {
            float4 a  = *(const float4*)&Qs[k * SM_STRIDE + 4 * r];
            float4 bb = *(const float4*)&Ks[k * SM_STRIDE + 4 * c];
            uint64_t pa[4] = {bcast2(a.x), bcast2(a.y), bcast2(a.z), bcast2(a.w)};
            uint64_t b0 = pack2(bb.x, bb.y);
            uint64_t b1 = pack2(bb.z, bb.w);
#pragma unroll
            for (int i = 0; i < 4; i++) {
                ffma2(s2[i][0], pa[i], b0);
                ffma2(s2[i][1], pa[i], b1);
            }
        }

        // Unpack, scale, mask.
        float s[4][4];
        const bool diag = (kt == qt);
#pragma unroll
        for (int i = 0; i < 4; i++) {
            float2 lo = unpack2(s2[i][0]);
            float2 hi = unpack2(s2[i][1]);
            s[i][0] = lo.x; s[i][1] = lo.y; s[i][2] = hi.x; s[i][3] = hi.y;
            int qg = q0 + 4 * r + i;
#pragma unroll
            for (int j = 0; j < 4; j++) {
                float v = s[i][j] * scale;
                if (diag && (kv0 + 4 * c + j > qg)) v = -1e30f;
                s[i][j] = v;
            }
        }

        // Online softmax per row (16 threads per row share the row via shuffle).
#pragma unroll
        for (int i = 0; i < 4; i++) {
            float mt = fmaxf(fmaxf(s[i][0], s[i][1]), fmaxf(s[i][2], s[i][3]));
#pragma unroll
            for (int w = 8; w >= 1; w >>= 1)
                mt = fmaxf(mt, __shfl_xor_sync(0xffffffffu, mt, w));
            float mn = fmaxf(m[i], mt);
            float alpha = __expf(m[i] - mn);
            float sum = 0.f;
#pragma unroll
            for (int j = 0; j < 4; j++) {
                float p = __expf(s[i][j] - mn);
                s[i][j] = p;
                sum += p;
            }
#pragma unroll
            for (int w = 8; w >= 1; w >>= 1)
                sum += __shfl_xor_sync(0xffffffffu, sum, w);
            l[i] = l[i] * alpha + sum;
            m[i] = mn;
            uint64_t pal = bcast2(alpha);
            mul2(o2[i][0], pal);
            mul2(o2[i][1], pal);
#pragma unroll
            for (int j = 0; j < 4; j++)
                Ps[(4 * r + i) * SM_STRIDE + 4 * c + j] = s[i][j];
        }
        __syncthreads();

        // O += P @ V  (k-unrolled by 4, packed FMA)
#pragma unroll 2
        for (int k0 = 0; k0 < 64; k0 += 4) {
            float4 pr[4], vv[4];
#pragma unroll
            for (int i = 0; i < 4; i++)
                pr[i] = *(const float4*)&Ps[(4 * r + i) * SM_STRIDE + k0];
#pragma unroll
            for (int kk = 0; kk < 4; kk++)
                vv[kk] = *(const float4*)&Vs[(k0 + kk) * SM_STRIDE + 4 * c];

            uint64_t pv[4][2];
#pragma unroll
            for (int kk = 0; kk < 4; kk++) {
                pv[kk][0] = pack2(vv[kk].x, vv[kk].y);
                pv[kk][1] = pack2(vv[kk].z, vv[kk].w);
            }
            float prf[4][4];
#pragma unroll
            for (int i = 0; i < 4; i++) {
                prf[i][0] = pr[i].x; prf[i][1] = pr[i].y;
                prf[i][2] = pr[i].z; prf[i][3] = pr[i].w;
            }
#pragma unroll
            for (int kk = 0; kk < 4; kk++)
#pragma unroll
                for (int i = 0; i < 4; i++) {
                    uint64_t pp = bcast2(prf[i][kk]);
                    ffma2(o2[i][0], pp, pv[kk][0]);
                    ffma2(o2[i][1], pp, pv[kk][1]);
                }
        }
    }

    // Epilogue: normalize + vector store.
#pragma unroll
    for (int i = 0; i < 4; i++) {
        float inv_l = 1.f / l[i];
        float2 lo = unpack2(o2[i][0]);
        float2 hi = unpack2(o2[i][1]);
        *(float4*)&out[((size_t)b * T_DIM + q0 + 4 * r + i) * H_DIM + 4 * c] =
            make_float4(lo.x * inv_l, lo.y * inv_l, hi.x * inv_l, hi.y * inv_l);
    }
}

// ---------------------------------------------------------------------------
extern "C" void kernel_launch(void* const* d_in, const int* in_sizes, int n_in,
                              void* d_out, int out_size)
{
    (void)in_sizes; (void)n_in; (void)out_size;
    const float* x  = (const float*)d_in[0];
    const float* Wq = (const float*)d_in[1];
    const float* Wk = (const float*)d_in[2];
    const float* Wv = (const float*)d_in[3];
    float* out = (float*)d_out;

    qkv_proj_kernel<<<(B_DIM * T_DIM) / 64, 256>>>(x, Wq, Wk, Wv);

    const int smem_bytes = 4 * TILE_ELEMS * (int)sizeof(float);  // 69632
    cudaFuncSetAttribute(attn_kernel,
                         cudaFuncAttributeMaxDynamicSharedMemorySize, smem_bytes);
    attn_kernel<<<(T_DIM / 64) * B_DIM, 256, smem_bytes>>>(out);
}

// round 7
// speedup vs baseline: 1.4638x; 1.1257x over previous
#include <cuda_runtime.h>
#include <cuda_bf16.h>
#include <stdint.h>

#define B_DIM 4
#define T_DIM 4096
#define C_DIM 1024
#define H_DIM 64
#define QTILE 128
#define KTILE 128
#define NQT (T_DIM / QTILE)   // 32

// Split-bf16 Q/K/V scratch (no cudaMalloc allowed -> device globals).
__device__ __align__(16) __nv_bfloat16 g_Qh[B_DIM * T_DIM * H_DIM];
__device__ __align__(16) __nv_bfloat16 g_Ql[B_DIM * T_DIM * H_DIM];
__device__ __align__(16) __nv_bfloat16 g_Kh[B_DIM * T_DIM * H_DIM];
__device__ __align__(16) __nv_bfloat16 g_Kl[B_DIM * T_DIM * H_DIM];
__device__ __align__(16) __nv_bfloat16 g_VTh[B_DIM * H_DIM * T_DIM];  // [b][d][t]
__device__ __align__(16) __nv_bfloat16 g_VTl[B_DIM * H_DIM * T_DIM];

// 1/sqrt(1024) * log2(e)  (softmax scale + base-2 exp folded into Q)
#define Q_SCALE 0.04508422002778f

__device__ __forceinline__ uint32_t smem_u32(const void* p) {
    uint32_t a;
    asm("{ .reg .u64 t; cvta.to.shared.u64 t, %1; cvt.u32.u64 %0, t; }"
        : "=r"(a) : "l"(p));
    return a;
}
__device__ __forceinline__ float ex2f(float x) {
    float y; asm("ex2.approx.ftz.f32 %0, %1;" : "=f"(y) : "f"(x)); return y;
}
__device__ __forceinline__ uint32_t pack_bf16(float a, float b) {
    __nv_bfloat162 t = __floats2bfloat162_rn(a, b);
    return *reinterpret_cast<uint32_t*>(&t);
}

__device__ __forceinline__ void ldsm_x4(uint32_t& r0, uint32_t& r1,
                                        uint32_t& r2, uint32_t& r3, uint32_t a) {
    asm volatile("ldmatrix.sync.aligned.m8n8.x4.shared.b16 {%0,%1,%2,%3}, [%4];"
                 : "=r"(r0), "=r"(r1), "=r"(r2), "=r"(r3) : "r"(a));
}
__device__ __forceinline__ void ldsm_x2(uint32_t& r0, uint32_t& r1, uint32_t a) {
    asm volatile("ldmatrix.sync.aligned.m8n8.x2.shared.b16 {%0,%1}, [%2];"
                 : "=r"(r0), "=r"(r1) : "r"(a));
}
__device__ __forceinline__ void mma16816(float* c, const uint32_t* a,
                                         uint32_t b0, uint32_t b1) {
    asm volatile("mma.sync.aligned.m16n8k16.row.col.f32.bf16.bf16.f32 "
                 "{%0,%1,%2,%3}, {%4,%5,%6,%7}, {%8,%9}, {%0,%1,%2,%3};"
                 : "+f"(c[0]), "+f"(c[1]), "+f"(c[2]), "+f"(c[3])
                 : "r"(a[0]), "r"(a[1]), "r"(a[2]), "r"(a[3]), "r"(b0), "r"(b1));
}

// ---------------------------------------------------------------------------
// QKV projection -> split bf16 outputs (Q pre-scaled, V transposed).
// Grid: (B*T)/64. Block 256.
// ---------------------------------------------------------------------------
__global__ __launch_bounds__(256) void qkv_proj_kernel(
    const float* __restrict__ x,
    const float* __restrict__ Wq,
    const float* __restrict__ Wk,
    const float* __restrict__ Wv)
{
    __shared__ float Xst[32][68];
    __shared__ float Ws[3][32][68];

    const float* Wm[3] = {Wq, Wk, Wv};
    const int row0 = blockIdx.x * 64;
    const int tid  = threadIdx.x;
    const int r    = tid >> 4;
    const int c    = tid & 15;

    float acc[4][3][4];
#pragma unroll
    for (int i = 0; i < 4; i++)
#pragma unroll
        for (int m = 0; m < 3; m++)
#pragma unroll
            for (int j = 0; j < 4; j++) acc[i][m][j] = 0.f;

    for (int k0 = 0; k0 < C_DIM; k0 += 32) {
#pragma unroll
        for (int it = 0; it < 2; it++) {
            int v = tid + it * 256;
            int row = v >> 3;
            int kq  = (v & 7) * 4;
            float4 xx = *(const float4*)&x[(size_t)(row0 + row) * C_DIM + k0 + kq];
            Xst[kq + 0][row] = xx.x; Xst[kq + 1][row] = xx.y;
            Xst[kq + 2][row] = xx.z; Xst[kq + 3][row] = xx.w;
        }
#pragma unroll
        for (int m = 0; m < 3; m++)
#pragma unroll
            for (int it = 0; it < 2; it++) {
                int v = tid + it * 256;
                int kk = v >> 4;
                int n  = (v & 15) * 4;
                *(float4*)&Ws[m][kk][n] =
                    *(const float4*)&Wm[m][(size_t)(k0 + kk) * H_DIM + n];
            }
        __syncthreads();

#pragma unroll 8
        for (int k = 0; k < 32; k++) {
            float4 a = *(const float4*)&Xst[k][4 * r];
            float av[4] = {a.x, a.y, a.z, a.w};
#pragma unroll
            for (int m = 0; m < 3; m++) {
                float4 bv = *(const float4*)&Ws[m][k][4 * c];
                float bb[4] = {bv.x, bv.y, bv.z, bv.w};
#pragma unroll
                for (int i = 0; i < 4; i++)
#pragma unroll
                    for (int j = 0; j < 4; j++)
                        acc[i][m][j] = fmaf(av[i], bb[j], acc[i][m][j]);
            }
        }
        __syncthreads();
    }

#pragma unroll
    for (int i = 0; i < 4; i++) {
        size_t grow = (size_t)(row0 + 4 * r + i) * H_DIM + 4 * c;
        float q[4], kv[4], qh[4], kh[4];
#pragma unroll
        for (int j = 0; j < 4; j++) { q[j] = acc[i][0][j] * Q_SCALE; kv[j] = acc[i][1][j]; }
#pragma unroll
        for (int j = 0; j < 4; j++) {
            qh[j] = __bfloat162float(__float2bfloat16(q[j]));
            kh[j] = __bfloat162float(__float2bfloat16(kv[j]));
        }
        *(uint2*)&g_Qh[grow] = make_uint2(pack_bf16(qh[0], qh[1]), pack_bf16(qh[2], qh[3]));
        *(uint2*)&g_Ql[grow] = make_uint2(pack_bf16(q[0] - qh[0], q[1] - qh[1]),
                                          pack_bf16(q[2] - qh[2], q[3] - qh[3]));
        *(uint2*)&g_Kh[grow] = make_uint2(pack_bf16(kh[0], kh[1]), pack_bf16(kh[2], kh[3]));
        *(uint2*)&g_Kl[grow] = make_uint2(pack_bf16(kv[0] - kh[0], kv[1] - kh[1]),
                                          pack_bf16(kv[2] - kh[2], kv[3] - kh[3]));
    }

    const int bb   = row0 >> 12;
    const int tloc = (row0 & (T_DIM - 1)) + 4 * r;
#pragma unroll
    for (int j = 0; j < 4; j++) {
        int d = 4 * c + j;
        size_t base = ((size_t)bb * H_DIM + d) * T_DIM + tloc;
        float v[4], vh[4];
#pragma unroll
        for (int i = 0; i < 4; i++) {
            v[i]  = acc[i][2][j];
            vh[i] = __bfloat162float(__float2bfloat16(v[i]));
        }
        *(uint2*)&g_VTh[base] = make_uint2(pack_bf16(vh[0], vh[1]), pack_bf16(vh[2], vh[3]));
        *(uint2*)&g_VTl[base] = make_uint2(pack_bf16(v[0] - vh[0], v[1] - vh[1]),
                                           pack_bf16(v[2] - vh[2], v[3] - vh[3]));
    }
}

// ---------------------------------------------------------------------------
// mma.sync flash attention. Grid 128 (qt desc x batch). Block 256 (8 warps).
// Each warp owns 16 q-rows. KTILE=128 kv per iteration, split-bf16 3-pass MMA.
// ---------------------------------------------------------------------------
// smem byte offsets: Q rows stride 144B, K rows stride 144B, VT rows stride 272B
#define SQH 0
#define SQL (SQH + 128 * 144)
#define SKH (SQL + 128 * 144)
#define SKL (SKH + 128 * 144)
#define SVH (SKL + 128 * 144)
#define SVL (SVH + 64 * 272)
#define SM_TOTAL (SVL + 64 * 272)   // 108544 bytes

__global__ __launch_bounds__(256) void attn_kernel(float* __restrict__ out)
{
    extern __shared__ char smem[];
    const uint32_t sb = smem_u32(smem);
    const int tid  = threadIdx.x;
    const int lane = tid & 31;
    const int w    = tid >> 5;          // warp id 0..7 -> rows 16w..16w+15
    const int gquad = lane >> 2;        // row group within warp
    const int tql   = lane & 3;         // thread in quad

    const int gblk = blockIdx.x;
    const int qt = (NQT - 1) - (gblk >> 2);
    const int b  = gblk & 3;
    const int q0 = qt * QTILE;

    // ---- load Q tile (split) into smem, 144B row stride ----
    {
        const char* qh = (const char*)(g_Qh + ((size_t)b * T_DIM + q0) * H_DIM);
        const char* ql = (const char*)(g_Ql + ((size_t)b * T_DIM + q0) * H_DIM);
#pragma unroll
        for (int it = 0; it < 4; it++) {
            int off = tid * 16 + it * 4096;
            int row = off >> 7, col = off & 127;
            *(uint4*)(smem + SQH + row * 144 + col) = *(const uint4*)(qh + off);
            *(uint4*)(smem + SQL + row * 144 + col) = *(const uint4*)(ql + off);
        }
    }

    float o[8][4];
#pragma unroll
    for (int d = 0; d < 8; d++)
#pragma unroll
        for (int e = 0; e < 4; e++) o[d][e] = 0.f;
    float m_a = -1e30f, m_b = -1e30f, l_a = 0.f, l_b = 0.f;

    const int row_a = q0 + 16 * w + gquad;      // global q row for c0,c1
    const int row_b = row_a + 8;                // for c2,c3

    for (int kt = 0; kt <= qt; kt++) {
        const int kv0 = kt * KTILE;
        __syncthreads();   // prior-iter smem consumers done (covers Q 1st iter)

        // ---- load K (split, 144B stride) and V^T (split, 272B stride) ----
        {
            const char* kh = (const char*)(g_Kh + ((size_t)b * T_DIM + kv0) * H_DIM);
            const char* kl = (const char*)(g_Kl + ((size_t)b * T_DIM + kv0) * H_DIM);
#pragma unroll
            for (int it = 0; it < 4; it++) {
                int off = tid * 16 + it * 4096;
                int row = off >> 7, col = off & 127;
                *(uint4*)(smem + SKH + row * 144 + col) = *(const uint4*)(kh + off);
                *(uint4*)(smem + SKL + row * 144 + col) = *(const uint4*)(kl + off);
            }
            const char* vh = (const char*)g_VTh + (size_t)b * H_DIM * T_DIM * 2 + (size_t)kv0 * 2;
            const char* vl = (const char*)g_VTl + (size_t)b * H_DIM * T_DIM * 2 + (size_t)kv0 * 2;
#pragma unroll
            for (int it = 0; it < 4; it++) {
                int off = tid * 16 + it * 4096;
                int d = off >> 8, col = off & 255;
                *(uint4*)(smem + SVH + d * 272 + col) =
                    *(const uint4*)(vh + (size_t)d * (T_DIM * 2) + col);
                *(uint4*)(smem + SVL + d * 272 + col) =
                    *(const uint4*)(vl + (size_t)d * (T_DIM * 2) + col);
            }
        }
        __syncthreads();

        // ---- S = Qh Kh^T + Qh Kl^T + Ql Kh^T  (m16 x n128 per warp) ----
        float s[16][4];
#pragma unroll
        for (int nb = 0; nb < 16; nb++)
#pragma unroll
            for (int e = 0; e < 4; e++) s[nb][e] = 0.f;

        const uint32_t a_row = 16 * w + (lane & 15);
        const uint32_t a_colb = (uint32_t)((lane >> 4) << 4);
#pragma unroll
        for (int ks = 0; ks < 4; ks++) {
            uint32_t ah[4], al[4];
            ldsm_x4(ah[0], ah[1], ah[2], ah[3],
                    sb + SQH + a_row * 144 + ks * 32 + a_colb);
            ldsm_x4(al[0], al[1], al[2], al[3],
                    sb + SQL + a_row * 144 + ks * 32 + a_colb);
            const uint32_t b_row = lane & 7;
            const uint32_t b_colb = (uint32_t)(((lane >> 3) & 1) << 4);
#pragma unroll
            for (int nb = 0; nb < 16; nb++) {
                uint32_t bh0, bh1, bl0, bl1;
                uint32_t baddr = (8 * nb + b_row) * 144 + ks * 32 + b_colb;
                ldsm_x2(bh0, bh1, sb + SKH + baddr);
                ldsm_x2(bl0, bl1, sb + SKL + baddr);
                mma16816(s[nb], ah, bh0, bh1);
                mma16816(s[nb], ah, bl0, bl1);
                mma16816(s[nb], al, bh0, bh1);
            }
        }

        // ---- causal mask (diagonal tile only) ----
        if (kt == qt) {
#pragma unroll
            for (int nb = 0; nb < 16; nb++) {
                int colg = kv0 + 8 * nb + 2 * tql;
                if (colg > row_a)     s[nb][0] = -1e30f;
                if (colg + 1 > row_a) s[nb][1] = -1e30f;
                if (colg > row_b)     s[nb][2] = -1e30f;
                if (colg + 1 > row_b) s[nb][3] = -1e30f;
            }
        }

        // ---- online softmax (base-2; scale folded into Q) ----
        float mt_a = -1e30f, mt_b = -1e30f;
#pragma unroll
        for (int nb = 0; nb < 16; nb++) {
            mt_a = fmaxf(mt_a, fmaxf(s[nb][0], s[nb][1]));
            mt_b = fmaxf(mt_b, fmaxf(s[nb][2], s[nb][3]));
        }
        mt_a = fmaxf(mt_a, __shfl_xor_sync(0xffffffffu, mt_a, 1));
        mt_a = fmaxf(mt_a, __shfl_xor_sync(0xffffffffu, mt_a, 2));
        mt_b = fmaxf(mt_b, __shfl_xor_sync(0xffffffffu, mt_b, 1));
        mt_b = fmaxf(mt_b, __shfl_xor_sync(0xffffffffu, mt_b, 2));

        float mn_a = fmaxf(m_a, mt_a), mn_b = fmaxf(m_b, mt_b);
        float al_a = ex2f(m_a - mn_a), al_b = ex2f(m_b - mn_b);
        m_a = mn_a; m_b = mn_b;

        float sum_a = 0.f, sum_b = 0.f;
#pragma unroll
        for (int nb = 0; nb < 16; nb++) {
            s[nb][0] = ex2f(s[nb][0] - mn_a);
            s[nb][1] = ex2f(s[nb][1] - mn_a);
            s[nb][2] = ex2f(s[nb][2] - mn_b);
            s[nb][3] = ex2f(s[nb][3] - mn_b);
            sum_a += s[nb][0] + s[nb][1];
            sum_b += s[nb][2] + s[nb][3];
        }
        sum_a += __shfl_xor_sync(0xffffffffu, sum_a, 1);
        sum_a += __shfl_xor_sync(0xffffffffu, sum_a, 2);
        sum_b += __shfl_xor_sync(0xffffffffu, sum_b, 1);
        sum_b += __shfl_xor_sync(0xffffffffu, sum_b, 2);
        l_a = l_a * al_a + sum_a;
        l_b = l_b * al_b + sum_b;

#pragma unroll
        for (int d = 0; d < 8; d++) {
            o[d][0] *= al_a; o[d][1] *= al_a;
            o[d][2] *= al_b; o[d][3] *= al_b;
        }

        // ---- O += Ph Vh + Ph Vl + Pl Vh  (P frags built from S in-register) ----
#pragma unroll
        for (int j = 0; j < 8; j++) {
            uint32_t ph[4], pl[4];
            float p00 = s[2 * j][0],     p01 = s[2 * j][1];
            float p02 = s[2 * j][2],     p03 = s[2 * j][3];
            float p10 = s[2 * j + 1][0], p11 = s[2 * j + 1][1];
            float p12 = s[2 * j + 1][2], p13 = s[2 * j + 1][3];
            float h00 = __bfloat162float(__float2bfloat16(p00));
            float h01 = __bfloat162float(__float2bfloat16(p01));
            float h02 = __bfloat162float(__float2bfloat16(p02));
            float h03 = __bfloat162float(__float2bfloat16(p03));
            float h10 = __bfloat162float(__float2bfloat16(p10));
            float h11 = __bfloat162float(__float2bfloat16(p11));
            float h12 = __bfloat162float(__float2bfloat16(p12));
            float h13 = __bfloat162float(__float2bfloat16(p13));
            ph[0] = pack_bf16(h00, h01);
            ph[1] = pack_bf16(h02, h03);
            ph[2] = pack_bf16(h10, h11);
            ph[3] = pack_bf16(h12, h13);
            pl[0] = pack_bf16(p00 - h00, p01 - h01);
            pl[1] = pack_bf16(p02 - h02, p03 - h03);
            pl[2] = pack_bf16(p10 - h10, p11 - h11);
            pl[3] = pack_bf16(p12 - h12, p13 - h13);

            const uint32_t v_row = lane & 7;
            const uint32_t v_colb = (uint32_t)(((lane >> 3) & 1) << 4);
#pragma unroll
            for (int d = 0; d < 8; d++) {
                uint32_t vaddr = (8 * d + v_row) * 272 + j * 32 + v_colb;
                uint32_t bh0, bh1, bl0, bl1;
                ldsm_x2(bh0, bh1, sb + SVH + vaddr);
                ldsm_x2(bl0, bl1, sb + SVL + vaddr);
                mma16816(o[d], ph, bh0, bh1);
                mma16816(o[d], ph, bl0, bl1);
                mma16816(o[d], pl, bh0, bh1);
            }
        }
    }

    // ---- epilogue ----
    float inv_a = 1.f / l_a, inv_b = 1.f / l_b;
#pragma unroll
    for (int d = 0; d < 8; d++) {
        size_t col = 8 * d + 2 * tql;
        *(float2*)&out[((size_t)b * T_DIM + row_a) * H_DIM + col] =
            make_float2(o[d][0] * inv_a, o[d][1] * inv_a);
        *(float2*)&out[((size_t)b * T_DIM + row_b) * H_DIM + col] =
            make_float2(o[d][2] * inv_b, o[d][3] * inv_b);
    }
}

// ---------------------------------------------------------------------------
extern "C" void kernel_launch(void* const* d_in, const int* in_sizes, int n_in,
                              void* d_out, int out_size)
{
    (void)in_sizes; (void)n_in; (void)out_size;
    const float* x  = (const float*)d_in[0];
    const float* Wq = (const float*)d_in[1];
    const float* Wk = (const float*)d_in[2];
    const float* Wv = (const float*)d_in[3];
    float* out = (float*)d_out;

    qkv_proj_kernel<<<(B_DIM * T_DIM) / 64, 256>>>(x, Wq, Wk, Wv);

    cudaFuncSetAttribute(attn_kernel,
                         cudaFuncAttributeMaxDynamicSharedMemorySize, SM_TOTAL);
    attn_kernel<<<NQT * B_DIM, 256, SM_TOTAL>>>(out);
}

// round 10
// speedup vs baseline: 2.4065x; 1.6440x over previous
#include <cuda_runtime.h>
#include <cuda_bf16.h>
#include <stdint.h>

#define B_DIM 4
#define T_DIM 4096
#define C_DIM 1024
#define H_DIM 64
#define QTILE 128
#define KTILE 128
#define NQT (T_DIM / QTILE)   // 32

__device__ __align__(16) __nv_bfloat16 g_Qh[B_DIM * T_DIM * H_DIM];
__device__ __align__(16) __nv_bfloat16 g_Ql[B_DIM * T_DIM * H_DIM];
__device__ __align__(16) __nv_bfloat16 g_Kh[B_DIM * T_DIM * H_DIM];
__device__ __align__(16) __nv_bfloat16 g_Kl[B_DIM * T_DIM * H_DIM];
__device__ __align__(16) __nv_bfloat16 g_VTh[B_DIM * H_DIM * T_DIM];  // [b][d][t]
__device__ __align__(16) __nv_bfloat16 g_VTl[B_DIM * H_DIM * T_DIM];

#define Q_SCALE 0.04508422002778f   // 1/sqrt(1024) * log2(e)

__device__ __forceinline__ uint32_t smem_u32(const void* p) {
    uint32_t a;
    asm("{ .reg .u64 t; cvta.to.shared.u64 t, %1; cvt.u32.u64 %0, t; }"
        : "=r"(a) : "l"(p));
    return a;
}
__device__ __forceinline__ float ex2f(float x) {
    float y; asm("ex2.approx.ftz.f32 %0, %1;" : "=f"(y) : "f"(x)); return y;
}
__device__ __forceinline__ uint32_t pack_bf16(float a, float b) {
    __nv_bfloat162 t = __floats2bfloat162_rn(a, b);
    return *reinterpret_cast<uint32_t*>(&t);
}
// packed f32x2 helpers
__device__ __forceinline__ uint64_t pack2(float x, float y) {
    uint64_t r; asm("mov.b64 %0, {%1, %2};" : "=l"(r) : "f"(x), "f"(y)); return r;
}
__device__ __forceinline__ uint64_t bcast2(float x) { return pack2(x, x); }
__device__ __forceinline__ void ffma2(uint64_t& d, uint64_t a, uint64_t b) {
    asm("fma.rn.f32x2 %0, %1, %2, %0;" : "+l"(d) : "l"(a), "l"(b));
}
__device__ __forceinline__ float2 unpack2(uint64_t v) {
    float2 f; asm("mov.b64 {%0, %1}, %2;" : "=f"(f.x), "=f"(f.y) : "l"(v)); return f;
}

__device__ __forceinline__ void ldsm_x4(uint32_t& r0, uint32_t& r1,
                                        uint32_t& r2, uint32_t& r3, uint32_t a) {
    asm volatile("ldmatrix.sync.aligned.m8n8.x4.shared.b16 {%0,%1,%2,%3}, [%4];"
                 : "=r"(r0), "=r"(r1), "=r"(r2), "=r"(r3) : "r"(a));
}
__device__ __forceinline__ void mma16816(float* c, const uint32_t* a,
                                         uint32_t b0, uint32_t b1) {
    asm volatile("mma.sync.aligned.m16n8k16.row.col.f32.bf16.bf16.f32 "
                 "{%0,%1,%2,%3}, {%4,%5,%6,%7}, {%8,%9}, {%0,%1,%2,%3};"
                 : "+f"(c[0]), "+f"(c[1]), "+f"(c[2]), "+f"(c[3])
                 : "r"(a[0]), "r"(a[1]), "r"(a[2]), "r"(a[3]), "r"(b0), "r"(b1));
}
__device__ __forceinline__ void cpa16(uint32_t s, const void* g) {
    asm volatile("cp.async.cg.shared.global [%0], [%1], 16;" :: "r"(s), "l"(g) : "memory");
}
#define CP_COMMIT asm volatile("cp.async.commit_group;" ::: "memory")
#define CP_WAIT1  asm volatile("cp.async.wait_group 1;" ::: "memory")
#define CP_WAIT0  asm volatile("cp.async.wait_group 0;" ::: "memory")

// ---------------------------------------------------------------------------
// QKV projection (FFMA2) -> split bf16; V transposed via smem, coalesced.
// Grid: (B*T)/64. Block 256.
// ---------------------------------------------------------------------------
__global__ __launch_bounds__(256) void qkv_proj_kernel(
    const float* __restrict__ x,
    const float* __restrict__ Wq,
    const float* __restrict__ Wk,
    const float* __restrict__ Wv)
{
    __shared__ __align__(16) float Xst[32][68];
    __shared__ __align__(16) float Ws[3][32][68];

    const float* Wm[3] = {Wq, Wk, Wv};
    const int row0 = blockIdx.x * 64;
    const int tid  = threadIdx.x;
    const int r    = tid >> 4;
    const int c    = tid & 15;

    uint64_t acc[4][3][2];
#pragma unroll
    for (int i = 0; i < 4; i++)
#pragma unroll
        for (int m = 0; m < 3; m++) { acc[i][m][0] = 0ull; acc[i][m][1] = 0ull; }

    for (int k0 = 0; k0 < C_DIM; k0 += 32) {
#pragma unroll
        for (int it = 0; it < 2; it++) {
            int v = tid + it * 256;
            int row = v >> 3;
            int kq  = (v & 7) * 4;
            float4 xx = *(const float4*)&x[(size_t)(row0 + row) * C_DIM + k0 + kq];
            Xst[kq + 0][row] = xx.x; Xst[kq + 1][row] = xx.y;
            Xst[kq + 2][row] = xx.z; Xst[kq + 3][row] = xx.w;
        }
#pragma unroll
        for (int m = 0; m < 3; m++)
#pragma unroll
            for (int it = 0; it < 2; it++) {
                int v = tid + it * 256;
                int kk = v >> 4;
                int n  = (v & 15) * 4;
                *(float4*)&Ws[m][kk][n] =
                    *(const float4*)&Wm[m][(size_t)(k0 + kk) * H_DIM + n];
            }
        __syncthreads();

#pragma unroll 8
        for (int k = 0; k < 32; k++) {
            float4 a = *(const float4*)&Xst[k][4 * r];
            uint64_t pa[4] = {bcast2(a.x), bcast2(a.y), bcast2(a.z), bcast2(a.w)};
#pragma unroll
            for (int m = 0; m < 3; m++) {
                float4 b = *(const float4*)&Ws[m][k][4 * c];
                uint64_t b0 = pack2(b.x, b.y);
                uint64_t b1 = pack2(b.z, b.w);
#pragma unroll
                for (int i = 0; i < 4; i++) {
                    ffma2(acc[i][m][0], pa[i], b0);
                    ffma2(acc[i][m][1], pa[i], b1);
                }
            }
        }
        __syncthreads();
    }

    // Q (scaled) and K: split hi/lo, direct coalesced-ish stores.
#pragma unroll
    for (int i = 0; i < 4; i++) {
        size_t grow = (size_t)(row0 + 4 * r + i) * H_DIM + 4 * c;
        float2 q01 = unpack2(acc[i][0][0]), q23 = unpack2(acc[i][0][1]);
        float2 k01 = unpack2(acc[i][1][0]), k23 = unpack2(acc[i][1][1]);
        float q[4] = {q01.x * Q_SCALE, q01.y * Q_SCALE, q23.x * Q_SCALE, q23.y * Q_SCALE};
        float kv[4] = {k01.x, k01.y, k23.x, k23.y};
        float qh[4], kh[4];
#pragma unroll
        for (int j = 0; j < 4; j++) {
            qh[j] = __bfloat162float(__float2bfloat16(q[j]));
            kh[j] = __bfloat162float(__float2bfloat16(kv[j]));
        }
        *(uint2*)&g_Qh[grow] = make_uint2(pack_bf16(qh[0], qh[1]), pack_bf16(qh[2], qh[3]));
        *(uint2*)&g_Ql[grow] = make_uint2(pack_bf16(q[0] - qh[0], q[1] - qh[1]),
                                          pack_bf16(q[2] - qh[2], q[3] - qh[3]));
        *(uint2*)&g_Kh[grow] = make_uint2(pack_bf16(kh[0], kh[1]), pack_bf16(kh[2], kh[3]));
        *(uint2*)&g_Kl[grow] = make_uint2(pack_bf16(kv[0] - kh[0], kv[1] - kh[1]),
                                          pack_bf16(kv[2] - kh[2], kv[3] - kh[3]));
    }

    // V: stage transposed in smem (reuse Ws), then coalesced 16B stores.
    __nv_bfloat16* Vsh = reinterpret_cast<__nv_bfloat16*>(Ws);          // [64][72]
    __nv_bfloat16* Vsl = Vsh + 64 * 72;
#pragma unroll
    for (int j = 0; j < 4; j++) {
        int d = 4 * c + j;
#pragma unroll
        for (int i = 0; i < 4; i++) {
            float2 v01 = unpack2(acc[i][2][0]), v23 = unpack2(acc[i][2][1]);
            float vf[4] = {v01.x, v01.y, v23.x, v23.y};
            float v = vf[j];
            float vh = __bfloat162float(__float2bfloat16(v));
            Vsh[d * 72 + 4 * r + i] = __float2bfloat16(vh);
            Vsl[d * 72 + 4 * r + i] = __float2bfloat16(v - vh);
        }
    }
    __syncthreads();

    const int bb    = row0 >> 12;
    const int tloc0 = row0 & (T_DIM - 1);
#pragma unroll
    for (int it = 0; it < 2; it++) {
        int idx = tid + it * 256;            // 512 chunks of 8 bf16
        int d   = idx >> 3;
        int ch  = (idx & 7) * 8;
        size_t gbase = ((size_t)bb * H_DIM + d) * T_DIM + tloc0 + ch;
        *(uint4*)&g_VTh[gbase] = *(uint4*)&Vsh[d * 72 + ch];
        *(uint4*)&g_VTl[gbase] = *(uint4*)&Vsl[d * 72 + ch];
    }
}

// ---------------------------------------------------------------------------
// mma.sync flash attention, cp.async double-buffered K/V.
// Grid 128 (qt desc x batch). Block 256 (8 warps, 16 q-rows each).
// ---------------------------------------------------------------------------
#define SQH 0
#define SQL (SQH + 128 * 144)
#define KST0 (SQL + 128 * 144)        // 36864
#define STG_SZ (18432 + 18432 + 17408 + 17408)   // 71680
#define SM_TOTAL (KST0 + 2 * STG_SZ)             // 180224

__global__ __launch_bounds__(256) void attn_kernel(float* __restrict__ out)
{
    extern __shared__ char smem[];
    const uint32_t sb = smem_u32(smem);
    const int tid  = threadIdx.x;
    const int lane = tid & 31;
    const int w    = tid >> 5;
    const int gquad = lane >> 2;
    const int tql   = lane & 3;
    const int lr    = lane & 7;        // ldsm row within 8x8
    const int lm    = lane >> 3;       // ldsm matrix index 0..3

    const int gblk = blockIdx.x;
    const int qt = (NQT - 1) - (gblk >> 2);
    const int b  = gblk & 3;
    const int q0 = qt * QTILE;

    const char* gqh = (const char*)(g_Qh + ((size_t)b * T_DIM + q0) * H_DIM);
    const char* gql = (const char*)(g_Ql + ((size_t)b * T_DIM + q0) * H_DIM);
    const char* gkh = (const char*)(g_Kh + (size_t)b * T_DIM * H_DIM);
    const char* gkl = (const char*)(g_Kl + (size_t)b * T_DIM * H_DIM);
    const char* gvh = (const char*)g_VTh + (size_t)b * H_DIM * T_DIM * 2;
    const char* gvl = (const char*)g_VTl + (size_t)b * H_DIM * T_DIM * 2;

    // ---- async load Q + stage 0 ----
#pragma unroll
    for (int it = 0; it < 4; it++) {
        int off = tid * 16 + it * 4096;
        int row = off >> 7, col = off & 127;
        cpa16(sb + SQH + row * 144 + col, gqh + off);
        cpa16(sb + SQL + row * 144 + col, gql + off);
    }
    {
        uint32_t skh = sb + KST0, skl = skh + 18432, svh = skl + 18432, svl = svh + 17408;
#pragma unroll
        for (int it = 0; it < 4; it++) {
            int off = tid * 16 + it * 4096;
            int row = off >> 7, col = off & 127;
            cpa16(skh + row * 144 + col, gkh + off);
            cpa16(skl + row * 144 + col, gkl + off);
            int d = off >> 8, vcol = off & 255;
            cpa16(svh + d * 272 + vcol, gvh + (size_t)d * (T_DIM * 2) + vcol);
            cpa16(svl + d * 272 + vcol, gvl + (size_t)d * (T_DIM * 2) + vcol);
        }
    }
    CP_COMMIT;

    float o[8][4];
#pragma unroll
    for (int d = 0; d < 8; d++)
#pragma unroll
        for (int e = 0; e < 4; e++) o[d][e] = 0.f;
    float m_a = -1e30f, m_b = -1e30f, l_a = 0.f, l_b = 0.f;

    const int row_a = q0 + 16 * w + gquad;
    const int row_b = row_a + 8;

    for (int kt = 0; kt <= qt; kt++) {
        const int kv0 = kt * KTILE;
        // prefetch next stage
        if (kt < qt) {
            int nkv0 = (kt + 1) * KTILE;
            uint32_t base = sb + KST0 + ((kt + 1) & 1) * STG_SZ;
            uint32_t skh = base, skl = base + 18432, svh = skl + 18432, svl = svh + 17408;
            const char* kh = gkh + (size_t)nkv0 * H_DIM * 2;
            const char* kl = gkl + (size_t)nkv0 * H_DIM * 2;
#pragma unroll
            for (int it = 0; it < 4; it++) {
                int off = tid * 16 + it * 4096;
                int row = off >> 7, col = off & 127;
                cpa16(skh + row * 144 + col, kh + off);
                cpa16(skl + row * 144 + col, kl + off);
                int d = off >> 8, vcol = off & 255;
                cpa16(svh + d * 272 + vcol, gvh + (size_t)d * (T_DIM * 2) + nkv0 * 2 + vcol);
                cpa16(svl + d * 272 + vcol, gvl + (size_t)d * (T_DIM * 2) + nkv0 * 2 + vcol);
            }
            CP_COMMIT;
            CP_WAIT1;
        } else {
            CP_WAIT0;
        }
        __syncthreads();

        const uint32_t stg = sb + KST0 + (kt & 1) * STG_SZ;
        const uint32_t skh = stg, skl = stg + 18432, svh = skl + 18432, svl = svh + 17408;

        // ---- S = Qh Kh^T + Qh Kl^T + Ql Kh^T ----
        float s[16][4];
#pragma unroll
        for (int nb = 0; nb < 16; nb++)
#pragma unroll
            for (int e = 0; e < 4; e++) s[nb][e] = 0.f;

        const uint32_t a_row = 16 * w + (lane & 15);
        const uint32_t a_colb = (uint32_t)((lane >> 4) << 4);
        // per-lane B address pieces: matrices (lm>>1) -> nb offset, (lm&1) -> k half
        const uint32_t b_nboff = (uint32_t)(lm >> 1);
        const uint32_t b_kh    = (uint32_t)((lm & 1) << 4);
#pragma unroll
        for (int ks = 0; ks < 4; ks++) {
            uint32_t ah[4], al[4];
            ldsm_x4(ah[0], ah[1], ah[2], ah[3], sb + SQH + a_row * 144 + ks * 32 + a_colb);
            ldsm_x4(al[0], al[1], al[2], al[3], sb + SQL + a_row * 144 + ks * 32 + a_colb);
#pragma unroll
            for (int nbp = 0; nbp < 8; nbp++) {
                int nb = 2 * nbp;
                uint32_t baddr = (8 * (nb + b_nboff) + lr) * 144 + ks * 32 + b_kh;
                uint32_t h0, h1, h2, h3, l0, l1, l2, l3;
                ldsm_x4(h0, h1, h2, h3, skh + baddr);
                ldsm_x4(l0, l1, l2, l3, skl + baddr);
                mma16816(s[nb], ah, h0, h1);
                mma16816(s[nb], ah, l0, l1);
                mma16816(s[nb], al, h0, h1);
                mma16816(s[nb + 1], ah, h2, h3);
                mma16816(s[nb + 1], ah, l2, l3);
                mma16816(s[nb + 1], al, h2, h3);
            }
        }

        // ---- causal mask (diagonal tile only) ----
        if (kt == qt) {
#pragma unroll
            for (int nb = 0; nb < 16; nb++) {
                int colg = kv0 + 8 * nb + 2 * tql;
                if (colg > row_a)     s[nb][0] = -1e30f;
                if (colg + 1 > row_a) s[nb][1] = -1e30f;
                if (colg > row_b)     s[nb][2] = -1e30f;
                if (colg + 1 > row_b) s[nb][3] = -1e30f;
            }
        }

        // ---- online softmax (base-2) ----
        float mt_a = -1e30f, mt_b = -1e30f;
#pragma unroll
        for (int nb = 0; nb < 16; nb++) {
            mt_a = fmaxf(mt_a, fmaxf(s[nb][0], s[nb][1]));
            mt_b = fmaxf(mt_b, fmaxf(s[nb][2], s[nb][3]));
        }
        mt_a = fmaxf(mt_a, __shfl_xor_sync(0xffffffffu, mt_a, 1));
        mt_a = fmaxf(mt_a, __shfl_xor_sync(0xffffffffu, mt_a, 2));
        mt_b = fmaxf(mt_b, __shfl_xor_sync(0xffffffffu, mt_b, 1));
        mt_b = fmaxf(mt_b, __shfl_xor_sync(0xffffffffu, mt_b, 2));

        float mn_a = fmaxf(m_a, mt_a), mn_b = fmaxf(m_b, mt_b);
        float al_a = ex2f(m_a - mn_a), al_b = ex2f(m_b - mn_b);
        m_a = mn_a; m_b = mn_b;

        float sum_a = 0.f, sum_b = 0.f;
#pragma unroll
        for (int nb = 0; nb < 16; nb++) {
            s[nb][0] = ex2f(s[nb][0] - mn_a);
            s[nb][1] = ex2f(s[nb][1] - mn_a);
            s[nb][2] = ex2f(s[nb][2] - mn_b);
            s[nb][3] = ex2f(s[nb][3] - mn_b);
            sum_a += s[nb][0] + s[nb][1];
            sum_b += s[nb][2] + s[nb][3];
        }
        sum_a += __shfl_xor_sync(0xffffffffu, sum_a, 1);
        sum_a += __shfl_xor_sync(0xffffffffu, sum_a, 2);
        sum_b += __shfl_xor_sync(0xffffffffu, sum_b, 1);
        sum_b += __shfl_xor_sync(0xffffffffu, sum_b, 2);
        l_a = l_a * al_a + sum_a;
        l_b = l_b * al_b + sum_b;

#pragma unroll
        for (int d = 0; d < 8; d++) {
            o[d][0] *= al_a; o[d][1] *= al_a;
            o[d][2] *= al_b; o[d][3] *= al_b;
        }

        // ---- O += Ph Vh + Ph Vl + Pl Vh ----
#pragma unroll
        for (int j = 0; j < 8; j++) {
            uint32_t ph[4], pl[4];
            float p00 = s[2 * j][0],     p01 = s[2 * j][1];
            float p02 = s[2 * j][2],     p03 = s[2 * j][3];
            float p10 = s[2 * j + 1][0], p11 = s[2 * j + 1][1];
            float p12 = s[2 * j + 1][2], p13 = s[2 * j + 1][3];
            float h00 = __bfloat162float(__float2bfloat16(p00));
            float h01 = __bfloat162float(__float2bfloat16(p01));
            float h02 = __bfloat162float(__float2bfloat16(p02));
            float h03 = __bfloat162float(__float2bfloat16(p03));
            float h10 = __bfloat162float(__float2bfloat16(p10));
            float h11 = __bfloat162float(__float2bfloat16(p11));
            float h12 = __bfloat162float(__float2bfloat16(p12));
            float h13 = __bfloat162float(__float2bfloat16(p13));
            ph[0] = pack_bf16(h00, h01);
            ph[1] = pack_bf16(h02, h03);
            ph[2] = pack_bf16(h10, h11);
            ph[3] = pack_bf16(h12, h13);
            pl[0] = pack_bf16(p00 - h00, p01 - h01);
            pl[1] = pack_bf16(p02 - h02, p03 - h03);
            pl[2] = pack_bf16(p10 - h10, p11 - h11);
            pl[3] = pack_bf16(p12 - h12, p13 - h13);

#pragma unroll
            for (int dp = 0; dp < 4; dp++) {
                int d = 2 * dp;
                uint32_t vaddr = (8 * (d + b_nboff) + lr) * 272 + j * 32 + b_kh;
                uint32_t h0, h1, h2, h3, l0, l1, l2, l3;
                ldsm_x4(h0, h1, h2, h3, svh + vaddr);
                ldsm_x4(l0, l1, l2, l3, svl + vaddr);
                mma16816(o[d], ph, h0, h1);
                mma16816(o[d], ph, l0, l1);
                mma16816(o[d], pl, h0, h1);
                mma16816(o[d + 1], ph, h2, h3);
                mma16816(o[d + 1], ph, l2, l3);
                mma16816(o[d + 1], pl, h2, h3);
            }
        }
        __syncthreads();   // all warps done with this stage before it is reloaded
    }

    float inv_a = 1.f / l_a, inv_b = 1.f / l_b;
#pragma unroll
    for (int d = 0; d < 8; d++) {
        size_t col = 8 * d + 2 * tql;
        *(float2*)&out[((size_t)b * T_DIM + row_a) * H_DIM + col] =
            make_float2(o[d][0] * inv_a, o[d][1] * inv_a);
        *(float2*)&out[((size_t)b * T_DIM + row_b) * H_DIM + col] =
            make_float2(o[d][2] * inv_b, o[d][3] * inv_b);
    }
}

// ---------------------------------------------------------------------------
extern "C" void kernel_launch(void* const* d_in, const int* in_sizes, int n_in,
                              void* d_out, int out_size)
{
    (void)in_sizes; (void)n_in; (void)out_size;
    const float* x  = (const float*)d_in[0];
    const float* Wq = (const float*)d_in[1];
    const float* Wk = (const float*)d_in[2];
    const float* Wv = (const float*)d_in[3];
    float* out = (float*)d_out;

    qkv_proj_kernel<<<(B_DIM * T_DIM) / 64, 256>>>(x, Wq, Wk, Wv);

    cudaFuncSetAttribute(attn_kernel,
                         cudaFuncAttributeMaxDynamicSharedMemorySize, SM_TOTAL);
    attn_kernel<<<NQT * B_DIM, 256, SM_TOTAL>>>(out);
}

// round 11
// speedup vs baseline: 3.6685x; 1.5244x over previous
#include <cuda_runtime.h>
#include <cuda_bf16.h>
#include <stdint.h>

#define B_DIM 4
#define T_DIM 4096
#define C_DIM 1024
#define H_DIM 64
#define QTILE 128
#define KTILE 128
#define NQT (T_DIM / QTILE)   // 32
#define GRID_W 148
#define NITEMS 320

// ---- device scratch (no cudaMalloc allowed) ----
__device__ __align__(16) __nv_bfloat16 g_xh[B_DIM * T_DIM * C_DIM];
__device__ __align__(16) __nv_bfloat16 g_xl[B_DIM * T_DIM * C_DIM];
__device__ __align__(16) __nv_bfloat16 g_wh[3 * C_DIM * H_DIM];
__device__ __align__(16) __nv_bfloat16 g_wl[3 * C_DIM * H_DIM];
__device__ __align__(16) __nv_bfloat16 g_Qh[B_DIM * T_DIM * H_DIM];
__device__ __align__(16) __nv_bfloat16 g_Ql[B_DIM * T_DIM * H_DIM];
__device__ __align__(16) __nv_bfloat16 g_Kh[B_DIM * T_DIM * H_DIM];
__device__ __align__(16) __nv_bfloat16 g_Kl[B_DIM * T_DIM * H_DIM];
__device__ __align__(16) __nv_bfloat16 g_VTh[B_DIM * H_DIM * T_DIM];  // [b][d][t]
__device__ __align__(16) __nv_bfloat16 g_VTl[B_DIM * H_DIM * T_DIM];
__device__ __align__(16) float  g_Op[4 * B_DIM * T_DIM * H_DIM];      // [p][b][t][d]
__device__ __align__(16) float2 g_ML[4 * B_DIM * T_DIM];              // [p][b][t]

#define Q_SCALE 0.04508422002778f   // 1/sqrt(1024) * log2(e)

__device__ __forceinline__ uint32_t smem_u32(const void* p) {
    uint32_t a;
    asm("{ .reg .u64 t; cvta.to.shared.u64 t, %1; cvt.u32.u64 %0, t; }"
        : "=r"(a) : "l"(p));
    return a;
}
__device__ __forceinline__ float ex2f(float x) {
    float y; asm("ex2.approx.ftz.f32 %0, %1;" : "=f"(y) : "f"(x)); return y;
}
__device__ __forceinline__ uint32_t pack_bf16(float a, float b) {
    __nv_bfloat162 t = __floats2bfloat162_rn(a, b);
    return *reinterpret_cast<uint32_t*>(&t);
}
__device__ __forceinline__ float bf_hi(float v) {
    return __bfloat162float(__float2bfloat16(v));
}
__device__ __forceinline__ void ldsm_x4(uint32_t& r0, uint32_t& r1,
                                        uint32_t& r2, uint32_t& r3, uint32_t a) {
    asm volatile("ldmatrix.sync.aligned.m8n8.x4.shared.b16 {%0,%1,%2,%3}, [%4];"
                 : "=r"(r0), "=r"(r1), "=r"(r2), "=r"(r3) : "r"(a));
}
__device__ __forceinline__ void ldsm_x4_t(uint32_t& r0, uint32_t& r1,
                                          uint32_t& r2, uint32_t& r3, uint32_t a) {
    asm volatile("ldmatrix.sync.aligned.m8n8.x4.trans.shared.b16 {%0,%1,%2,%3}, [%4];"
                 : "=r"(r0), "=r"(r1), "=r"(r2), "=r"(r3) : "r"(a));
}
__device__ __forceinline__ void mma16816(float* c, const uint32_t* a,
                                         uint32_t b0, uint32_t b1) {
    asm volatile("mma.sync.aligned.m16n8k16.row.col.f32.bf16.bf16.f32 "
                 "{%0,%1,%2,%3}, {%4,%5,%6,%7}, {%8,%9}, {%0,%1,%2,%3};"
                 : "+f"(c[0]), "+f"(c[1]), "+f"(c[2]), "+f"(c[3])
                 : "r"(a[0]), "r"(a[1]), "r"(a[2]), "r"(a[3]), "r"(b0), "r"(b1));
}
__device__ __forceinline__ void cpa16(uint32_t s, const void* g) {
    asm volatile("cp.async.cg.shared.global [%0], [%1], 16;" :: "r"(s), "l"(g) : "memory");
}
#define CP_COMMIT asm volatile("cp.async.commit_group;" ::: "memory")
#define CP_WAIT1  asm volatile("cp.async.wait_group 1;" ::: "memory")
#define CP_WAIT0  asm volatile("cp.async.wait_group 0;" ::: "memory")

// ---------------------------------------------------------------------------
// Split x into bf16 hi/lo. 16M floats; grid 4096 x 256, 4 float4/thread.
// ---------------------------------------------------------------------------
__global__ __launch_bounds__(256) void splitx_kernel(const float* __restrict__ x)
{
    size_t t0 = (size_t)blockIdx.x * 256 + threadIdx.x;
#pragma unroll
    for (int it = 0; it < 4; it++) {
        size_t i = t0 + (size_t)it * 1048576;
        float4 v = ((const float4*)x)[i];
        float h0 = bf_hi(v.x), h1 = bf_hi(v.y), h2 = bf_hi(v.z), h3 = bf_hi(v.w);
        ((uint2*)g_xh)[i] = make_uint2(pack_bf16(h0, h1), pack_bf16(h2, h3));
        ((uint2*)g_xl)[i] = make_uint2(pack_bf16(v.x - h0, v.y - h1),
                                       pack_bf16(v.z - h2, v.w - h3));
    }
}

// Split W (3 x 1024 x 64) into bf16 hi/lo. grid 192 x 256, 1 float4/thread.
__global__ __launch_bounds__(256) void splitw_kernel(
    const float* __restrict__ Wq, const float* __restrict__ Wk,
    const float* __restrict__ Wv)
{
    int idx = blockIdx.x * 256 + threadIdx.x;          // < 49152 float4
    int m = idx >> 14;
    int rem = idx & 16383;
    const float* W = (m == 0) ? Wq : (m == 1) ? Wk : Wv;
    float4 v = ((const float4*)W)[rem];
    float h0 = bf_hi(v.x), h1 = bf_hi(v.y), h2 = bf_hi(v.z), h3 = bf_hi(v.w);
    ((uint2*)g_wh)[idx] = make_uint2(pack_bf16(h0, h1), pack_bf16(h2, h3));
    ((uint2*)g_wl)[idx] = make_uint2(pack_bf16(v.x - h0, v.y - h1),
                                     pack_bf16(v.z - h2, v.w - h3));
}

// ---------------------------------------------------------------------------
// QKV projection via mma.sync split-bf16. Grid 128 (128 rows each), block 256.
// Out = x[128,1024] @ W[1024,192], 3-pass split. Epilogue emits split Q/K/VT.
// ---------------------------------------------------------------------------
#define PXH 0
#define PXL 18432
#define PWH 36864
#define PWL 62464
#define PSTG 88064
#define PSM_TOTAL (2 * PSTG)   // 176128

__global__ __launch_bounds__(256) void proj_kernel()
{
    extern __shared__ char smem[];
    const uint32_t sb = smem_u32(smem);
    const int tid  = threadIdx.x;
    const int lane = tid & 31;
    const int w    = tid >> 5;
    const int gquad = lane >> 2;
    const int tql   = lane & 3;
    const int lr    = lane & 7;
    const uint32_t kofs = (uint32_t)(((lane >> 3) & 1) << 3);  // 0/8 k
    const uint32_t nofs = (uint32_t)((lane >> 4) << 3);        // 0/8 n

    const int row0 = blockIdx.x * 128;

    // stage loader: X rows 128x64 bf16 (144B stride), W 64x192 bf16 (400B stride)
    auto load_stage = [&](int kc, int st) {
        uint32_t base = sb + st * PSTG;
        const __nv_bfloat16* xh = g_xh + (size_t)row0 * C_DIM + kc * 64;
        const __nv_bfloat16* xl = g_xl + (size_t)row0 * C_DIM + kc * 64;
#pragma unroll
        for (int it = 0; it < 4; it++) {
            int idx = tid + it * 256;          // 1024: row(128) x seg(8)
            int row = idx >> 3, seg = idx & 7;
            cpa16(base + PXH + row * 144 + seg * 16, xh + (size_t)row * C_DIM + seg * 8);
            cpa16(base + PXL + row * 144 + seg * 16, xl + (size_t)row * C_DIM + seg * 8);
        }
#pragma unroll
        for (int it = 0; it < 6; it++) {
            int idx = tid + it * 256;          // 1536: kr(64) x s24(24)
            int kr = idx / 24, s24 = idx - kr * 24;
            int m = s24 >> 3, seg = s24 & 7;
            size_t gsrc = ((size_t)m * C_DIM + kc * 64 + kr) * H_DIM + seg * 8;
            cpa16(base + PWH + kr * 400 + s24 * 16, g_wh + gsrc);
            cpa16(base + PWL + kr * 400 + s24 * 16, g_wl + gsrc);
        }
    };

    load_stage(0, 0);
    CP_COMMIT;

    float s[24][4];
#pragma unroll
    for (int nb = 0; nb < 24; nb++)
#pragma unroll
        for (int e = 0; e < 4; e++) s[nb][e] = 0.f;

    const uint32_t a_row = 16 * w + (lane & 15);
    const uint32_t a_colb = (uint32_t)((lane >> 4) << 4);

    for (int kc = 0; kc < 16; kc++) {
        if (kc < 15) { load_stage(kc + 1, (kc + 1) & 1); CP_COMMIT; CP_WAIT1; }
        else         { CP_WAIT0; }
        __syncthreads();
        const uint32_t base = sb + (kc & 1) * PSTG;
#pragma unroll
        for (int ks = 0; ks < 4; ks++) {
            uint32_t ah[4], al[4];
            ldsm_x4(ah[0], ah[1], ah[2], ah[3], base + PXH + a_row * 144 + ks * 32 + a_colb);
            ldsm_x4(al[0], al[1], al[2], al[3], base + PXL + a_row * 144 + ks * 32 + a_colb);
            const uint32_t wrow = (uint32_t)(ks * 16) + kofs + lr;
#pragma unroll
            for (int np = 0; np < 12; np++) {
                uint32_t woff = wrow * 400 + (np * 16 + nofs) * 2;
                uint32_t h0, h1, h2, h3, l0, l1, l2, l3;
                ldsm_x4_t(h0, h1, h2, h3, base + PWH + woff);
                ldsm_x4_t(l0, l1, l2, l3, base + PWL + woff);
                mma16816(s[2 * np], ah, h0, h1);
                mma16816(s[2 * np], ah, l0, l1);
                mma16816(s[2 * np], al, h0, h1);
                mma16816(s[2 * np + 1], ah, h2, h3);
                mma16816(s[2 * np + 1], ah, l2, l3);
                mma16816(s[2 * np + 1], al, h2, h3);
            }
        }
        __syncthreads();
    }

    // ---- epilogue: Q (scaled) + K split stores; V staged transposed ----
    const int ra = 16 * w + gquad;     // local rows
    const int rb = ra + 8;
    const size_t ga = (size_t)(row0 + ra) * H_DIM;
    const size_t gb = (size_t)(row0 + rb) * H_DIM;

#pragma unroll
    for (int nb = 0; nb < 8; nb++) {   // Q
        int col = 8 * nb + 2 * tql;
        float q0 = s[nb][0] * Q_SCALE, q1 = s[nb][1] * Q_SCALE;
        float q2 = s[nb][2] * Q_SCALE, q3 = s[nb][3] * Q_SCALE;
        float h0 = bf_hi(q0), h1 = bf_hi(q1), h2 = bf_hi(q2), h3 = bf_hi(q3);
        *(uint32_t*)&g_Qh[ga + col] = pack_bf16(h0, h1);
        *(uint32_t*)&g_Ql[ga + col] = pack_bf16(q0 - h0, q1 - h1);
        *(uint32_t*)&g_Qh[gb + col] = pack_bf16(h2, h3);
        *(uint32_t*)&g_Ql[gb + col] = pack_bf16(q2 - h2, q3 - h3);
    }
#pragma unroll
    for (int nb = 8; nb < 16; nb++) {  // K
        int col = 8 * (nb - 8) + 2 * tql;
        float k0 = s[nb][0], k1 = s[nb][1], k2 = s[nb][2], k3 = s[nb][3];
        float h0 = bf_hi(k0), h1 = bf_hi(k1), h2 = bf_hi(k2), h3 = bf_hi(k3);
        *(uint32_t*)&g_Kh[ga + col] = pack_bf16(h0, h1);
        *(uint32_t*)&g_Kl[ga + col] = pack_bf16(k0 - h0, k1 - h1);
        *(uint32_t*)&g_Kh[gb + col] = pack_bf16(h2, h3);
        *(uint32_t*)&g_Kl[gb + col] = pack_bf16(k2 - h2, k3 - h3);
    }
    // V: stage transposed [64 d][128 t] (272B stride), aliases stage-0 smem.
    __nv_bfloat16* VSH = (__nv_bfloat16*)smem;
    __nv_bfloat16* VSL = (__nv_bfloat16*)(smem + 17408);
#pragma unroll
    for (int nb = 16; nb < 24; nb++) {
        int d0 = 8 * (nb - 16) + 2 * tql;
        float v0 = s[nb][0], v1 = s[nb][1], v2 = s[nb][2], v3 = s[nb][3];
        float h0 = bf_hi(v0), h1 = bf_hi(v1), h2 = bf_hi(v2), h3 = bf_hi(v3);
        *(__nv_bfloat16*)((char*)VSH + d0 * 272 + ra * 2)       = __float2bfloat16(h0);
        *(__nv_bfloat16*)((char*)VSH + (d0 + 1) * 272 + ra * 2) = __float2bfloat16(h1);
        *(__nv_bfloat16*)((char*)VSH + d0 * 272 + rb * 2)       = __float2bfloat16(h2);
        *(__nv_bfloat16*)((char*)VSH + (d0 + 1) * 272 + rb * 2) = __float2bfloat16(h3);
        *(__nv_bfloat16*)((char*)VSL + d0 * 272 + ra * 2)       = __float2bfloat16(v0 - h0);
        *(__nv_bfloat16*)((char*)VSL + (d0 + 1) * 272 + ra * 2) = __float2bfloat16(v1 - h1);
        *(__nv_bfloat16*)((char*)VSL + d0 * 272 + rb * 2)       = __float2bfloat16(v2 - h2);
        *(__nv_bfloat16*)((char*)VSL + (d0 + 1) * 272 + rb * 2) = __float2bfloat16(v3 - h3);
    }
    __syncthreads();
    const int bI = row0 >> 12;
    const int t0 = row0 & (T_DIM - 1);
#pragma unroll
    for (int it = 0; it < 4; it++) {
        int idx = tid + it * 256;          // 1024: d(64) x seg(16)
        int d = idx >> 4, seg = idx & 15;
        size_t gdst = ((size_t)(bI * H_DIM + d)) * T_DIM + t0 + seg * 8;
        *(uint4*)&g_VTh[gdst] = *(uint4*)((char*)VSH + d * 272 + seg * 16);
        *(uint4*)&g_VTl[gdst] = *(uint4*)((char*)VSL + d * 272 + seg * 16);
    }
}

// ---------------------------------------------------------------------------
// Flash attention, balanced items. Grid GRID_W, block 256 (8 warps).
// Items: (b, qt, p) with qt split into qt/8+1 even kv chunks; partials out.
// ---------------------------------------------------------------------------
#define SQH 0
#define SQL (SQH + 128 * 144)
#define KST0 (SQL + 128 * 144)        // 36864
#define STG_SZ (18432 + 18432 + 17408 + 17408)   // 71680
#define SM_TOTAL (KST0 + 2 * STG_SZ)             // 180224

__global__ __launch_bounds__(256) void attn_kernel()
{
    extern __shared__ char smem[];
    const uint32_t sb = smem_u32(smem);
    const int tid  = threadIdx.x;
    const int lane = tid & 31;
    const int w    = tid >> 5;
    const int gquad = lane >> 2;
    const int tql   = lane & 3;
    const int lr    = lane & 7;
    const int lm    = lane >> 3;
    const uint32_t b_nboff = (uint32_t)(lm >> 1);
    const uint32_t b_kh    = (uint32_t)((lm & 1) << 4);
    const uint32_t a_row   = 16 * w + (lane & 15);
    const uint32_t a_colb  = (uint32_t)((lane >> 4) << 4);

    for (int item = blockIdx.x; item < NITEMS; item += GRID_W) {
        // ---- decode (qt descending = heavy first) ----
        int qt, b, p;
        if (item < 128)      { qt = 31 - (item >> 4); int r = item & 15; p = r >> 2; b = r & 3; }
        else if (item < 224) { int j = item - 128; int q = j / 12; qt = 23 - q;
                               int r = j - q * 12; p = r >> 2; b = r & 3; }
        else if (item < 288) { int j = item - 224; qt = 15 - (j >> 3);
                               int r = j & 7; p = r >> 2; b = r & 3; }
        else                 { int j = item - 288; qt = 7 - (j >> 2); p = 0; b = j & 3; }
        const int np  = (qt >> 3) + 1;
        const int kt0 = p * (qt + 1) / np;
        const int kt1 = (p + 1) * (qt + 1) / np;
        const int q0  = qt * QTILE;

        const char* gqh = (const char*)(g_Qh + ((size_t)b * T_DIM + q0) * H_DIM);
        const char* gql = (const char*)(g_Ql + ((size_t)b * T_DIM + q0) * H_DIM);
        const char* gkh = (const char*)(g_Kh + (size_t)b * T_DIM * H_DIM);
        const char* gkl = (const char*)(g_Kl + (size_t)b * T_DIM * H_DIM);
        const char* gvh = (const char*)g_VTh + (size_t)b * H_DIM * T_DIM * 2;
        const char* gvl = (const char*)g_VTl + (size_t)b * H_DIM * T_DIM * 2;

        // ---- prologue: Q + first stage ----
#pragma unroll
        for (int it = 0; it < 4; it++) {
            int off = tid * 16 + it * 4096;
            int row = off >> 7, col = off & 127;
            cpa16(sb + SQH + row * 144 + col, gqh + off);
            cpa16(sb + SQL + row * 144 + col, gql + off);
        }
        {
            uint32_t skh = sb + KST0, skl = skh + 18432, svh = skl + 18432, svl = svh + 17408;
            const char* kh = gkh + (size_t)kt0 * KTILE * H_DIM * 2;
            const char* kl = gkl + (size_t)kt0 * KTILE * H_DIM * 2;
#pragma unroll
            for (int it = 0; it < 4; it++) {
                int off = tid * 16 + it * 4096;
                int row = off >> 7, col = off & 127;
                cpa16(skh + row * 144 + col, kh + off);
                cpa16(skl + row * 144 + col, kl + off);
                int d = off >> 8, vcol = off & 255;
                cpa16(svh + d * 272 + vcol,
                      gvh + (size_t)d * (T_DIM * 2) + kt0 * KTILE * 2 + vcol);
                cpa16(svl + d * 272 + vcol,
                      gvl + (size_t)d * (T_DIM * 2) + kt0 * KTILE * 2 + vcol);
            }
        }
        CP_COMMIT;

        float o[8][4];
#pragma unroll
        for (int d = 0; d < 8; d++)
#pragma unroll
            for (int e = 0; e < 4; e++) o[d][e] = 0.f;
        float m_a = -1e30f, m_b = -1e30f, l_a = 0.f, l_b = 0.f;

        const int row_a = q0 + 16 * w + gquad;
        const int row_b = row_a + 8;

        for (int kt = kt0; kt < kt1; kt++) {
            const int kv0 = kt * KTILE;
            if (kt + 1 < kt1) {
                int nkv0 = (kt + 1) * KTILE;
                uint32_t base = sb + KST0 + ((kt + 1 - kt0) & 1) * STG_SZ;
                uint32_t skh = base, skl = base + 18432, svh = skl + 18432, svl = svh + 17408;
                const char* kh = gkh + (size_t)nkv0 * H_DIM * 2;
                const char* kl = gkl + (size_t)nkv0 * H_DIM * 2;
#pragma unroll
                for (int it = 0; it < 4; it++) {
                    int off = tid * 16 + it * 4096;
                    int row = off >> 7, col = off & 127;
                    cpa16(skh + row * 144 + col, kh + off);
                    cpa16(skl + row * 144 + col, kl + off);
                    int d = off >> 8, vcol = off & 255;
                    cpa16(svh + d * 272 + vcol, gvh + (size_t)d * (T_DIM * 2) + nkv0 * 2 + vcol);
                    cpa16(svl + d * 272 + vcol, gvl + (size_t)d * (T_DIM * 2) + nkv0 * 2 + vcol);
                }
                CP_COMMIT;
                CP_WAIT1;
            } else {
                CP_WAIT0;
            }
            __syncthreads();

            const uint32_t stg = sb + KST0 + ((kt - kt0) & 1) * STG_SZ;
            const uint32_t skh = stg, skl = stg + 18432, svh = skl + 18432, svl = svh + 17408;

            // ---- S = Qh Kh^T + Qh Kl^T + Ql Kh^T ----
            float s[16][4];
#pragma unroll
            for (int nb = 0; nb < 16; nb++)
#pragma unroll
                for (int e = 0; e < 4; e++) s[nb][e] = 0.f;

#pragma unroll
            for (int ks = 0; ks < 4; ks++) {
                uint32_t ah[4], al[4];
                ldsm_x4(ah[0], ah[1], ah[2], ah[3], sb + SQH + a_row * 144 + ks * 32 + a_colb);
                ldsm_x4(al[0], al[1], al[2], al[3], sb + SQL + a_row * 144 + ks * 32 + a_colb);
#pragma unroll
                for (int nbp = 0; nbp < 8; nbp++) {
                    int nb = 2 * nbp;
                    uint32_t baddr = (8 * (nb + b_nboff) + lr) * 144 + ks * 32 + b_kh;
                    uint32_t h0, h1, h2, h3, l0, l1, l2, l3;
                    ldsm_x4(h0, h1, h2, h3, skh + baddr);
                    ldsm_x4(l0, l1, l2, l3, skl + baddr);
                    mma16816(s[nb], ah, h0, h1);
                    mma16816(s[nb], ah, l0, l1);
                    mma16816(s[nb], al, h0, h1);
                    mma16816(s[nb + 1], ah, h2, h3);
                    mma16816(s[nb + 1], ah, l2, l3);
                    mma16816(s[nb + 1], al, h2, h3);
                }
            }

            if (kt == qt) {
#pragma unroll
                for (int nb = 0; nb < 16; nb++) {
                    int colg = kv0 + 8 * nb + 2 * tql;
                    if (colg > row_a)     s[nb][0] = -1e30f;
                    if (colg + 1 > row_a) s[nb][1] = -1e30f;
                    if (colg > row_b)     s[nb][2] = -1e30f;
                    if (colg + 1 > row_b) s[nb][3] = -1e30f;
                }
            }

            // ---- online softmax (base-2) ----
            float mt_a = -1e30f, mt_b = -1e30f;
#pragma unroll
            for (int nb = 0; nb < 16; nb++) {
                mt_a = fmaxf(mt_a, fmaxf(s[nb][0], s[nb][1]));
                mt_b = fmaxf(mt_b, fmaxf(s[nb][2], s[nb][3]));
            }
            mt_a = fmaxf(mt_a, __shfl_xor_sync(0xffffffffu, mt_a, 1));
            mt_a = fmaxf(mt_a, __shfl_xor_sync(0xffffffffu, mt_a, 2));
            mt_b = fmaxf(mt_b, __shfl_xor_sync(0xffffffffu, mt_b, 1));
            mt_b = fmaxf(mt_b, __shfl_xor_sync(0xffffffffu, mt_b, 2));

            float mn_a = fmaxf(m_a, mt_a), mn_b = fmaxf(m_b, mt_b);
            float al_a = ex2f(m_a - mn_a), al_b = ex2f(m_b - mn_b);
            m_a = mn_a; m_b = mn_b;

            float sum_a = 0.f, sum_b = 0.f;
#pragma unroll
            for (int nb = 0; nb < 16; nb++) {
                s[nb][0] = ex2f(s[nb][0] - mn_a);
                s[nb][1] = ex2f(s[nb][1] - mn_a);
                s[nb][2] = ex2f(s[nb][2] - mn_b);
                s[nb][3] = ex2f(s[nb][3] - mn_b);
                sum_a += s[nb][0] + s[nb][1];
                sum_b += s[nb][2] + s[nb][3];
            }
            sum_a += __shfl_xor_sync(0xffffffffu, sum_a, 1);
            sum_a += __shfl_xor_sync(0xffffffffu, sum_a, 2);
            sum_b += __shfl_xor_sync(0xffffffffu, sum_b, 1);
            sum_b += __shfl_xor_sync(0xffffffffu, sum_b, 2);
            l_a = l_a * al_a + sum_a;
            l_b = l_b * al_b + sum_b;

#pragma unroll
            for (int d = 0; d < 8; d++) {
                o[d][0] *= al_a; o[d][1] *= al_a;
                o[d][2] *= al_b; o[d][3] *= al_b;
            }

            // ---- O += Ph Vh + Ph Vl + Pl Vh ----
#pragma unroll
            for (int j = 0; j < 8; j++) {
                uint32_t ph[4], pl[4];
                float p00 = s[2 * j][0],     p01 = s[2 * j][1];
                float p02 = s[2 * j][2],     p03 = s[2 * j][3];
                float p10 = s[2 * j + 1][0], p11 = s[2 * j + 1][1];
                float p12 = s[2 * j + 1][2], p13 = s[2 * j + 1][3];
                float h00 = bf_hi(p00), h01 = bf_hi(p01), h02 = bf_hi(p02), h03 = bf_hi(p03);
                float h10 = bf_hi(p10), h11 = bf_hi(p11), h12 = bf_hi(p12), h13 = bf_hi(p13);
                ph[0] = pack_bf16(h00, h01); ph[1] = pack_bf16(h02, h03);
                ph[2] = pack_bf16(h10, h11); ph[3] = pack_bf16(h12, h13);
                pl[0] = pack_bf16(p00 - h00, p01 - h01);
                pl[1] = pack_bf16(p02 - h02, p03 - h03);
                pl[2] = pack_bf16(p10 - h10, p11 - h11);
                pl[3] = pack_bf16(p12 - h12, p13 - h13);
#pragma unroll
                for (int dp = 0; dp < 4; dp++) {
                    int d = 2 * dp;
                    uint32_t vaddr = (8 * (d + b_nboff) + lr) * 272 + j * 32 + b_kh;
                    uint32_t h0, h1, h2, h3, l0, l1, l2, l3;
                    ldsm_x4(h0, h1, h2, h3, svh + vaddr);
                    ldsm_x4(l0, l1, l2, l3, svl + vaddr);
                    mma16816(o[d], ph, h0, h1);
                    mma16816(o[d], ph, l0, l1);
                    mma16816(o[d], pl, h0, h1);
                    mma16816(o[d + 1], ph, h2, h3);
                    mma16816(o[d + 1], ph, l2, l3);
                    mma16816(o[d + 1], pl, h2, h3);
                }
            }
            __syncthreads();
        }

        // ---- partial epilogue ----
        {
            float* Op = g_Op + (size_t)(p * B_DIM + b) * T_DIM * H_DIM;
            float2* MLp = g_ML + (size_t)(p * B_DIM + b) * T_DIM;
#pragma unroll
            for (int d = 0; d < 8; d++) {
                int col = 8 * d + 2 * tql;
                *(float2*)&Op[(size_t)row_a * H_DIM + col] = make_float2(o[d][0], o[d][1]);
                *(float2*)&Op[(size_t)row_b * H_DIM + col] = make_float2(o[d][2], o[d][3]);
            }
            if (tql == 0) {
                MLp[row_a] = make_float2(m_a, l_a);
                MLp[row_b] = make_float2(m_b, l_b);
            }
        }
    }
}

// ---------------------------------------------------------------------------
// Combine partials -> out. Grid 4096 x 256 (one thread per output element).
// ---------------------------------------------------------------------------
__global__ __launch_bounds__(256) void combine_kernel(float* __restrict__ out)
{
    int idx = blockIdx.x * 256 + threadIdx.x;   // < 4*4096*64
    int col = idx & 63;
    int pr  = idx >> 6;         // [0, 16384): b*4096 + t
    int b   = pr >> 12;
    int t   = pr & (T_DIM - 1);
    int qt  = t >> 7;
    int np  = (qt >> 3) + 1;

    float m = -1e30f;
    for (int p = 0; p < np; p++)
        m = fmaxf(m, g_ML[(size_t)(p * B_DIM + b) * T_DIM + t].x);
    float l = 0.f, ov = 0.f;
    for (int p = 0; p < np; p++) {
        float2 ml = g_ML[(size_t)(p * B_DIM + b) * T_DIM + t];
        float wgt = ex2f(ml.x - m);
        l += ml.y * wgt;
        ov += g_Op[((size_t)(p * B_DIM + b) * T_DIM + t) * H_DIM + col] * wgt;
    }
    out[((size_t)b * T_DIM + t) * H_DIM + col] = ov / l;
}

// ---------------------------------------------------------------------------
extern "C" void kernel_launch(void* const* d_in, const int* in_sizes, int n_in,
                              void* d_out, int out_size)
{
    (void)in_sizes; (void)n_in; (void)out_size;
    const float* x  = (const float*)d_in[0];
    const float* Wq = (const float*)d_in[1];
    const float* Wk = (const float*)d_in[2];
    const float* Wv = (const float*)d_in[3];
    float* out = (float*)d_out;

    splitx_kernel<<<4096, 256>>>(x);
    splitw_kernel<<<192, 256>>>(Wq, Wk, Wv);

    cudaFuncSetAttribute(proj_kernel,
                         cudaFuncAttributeMaxDynamicSharedMemorySize, PSM_TOTAL);
    proj_kernel<<<128, 256, PSM_TOTAL>>>();

    cudaFuncSetAttribute(attn_kernel,
                         cudaFuncAttributeMaxDynamicSharedMemorySize, SM_TOTAL);
    attn_kernel<<<GRID_W, 256, SM_TOTAL>>>();

    combine_kernel<<<4096, 256>>>(out);
}

// round 13
// speedup vs baseline: 4.4924x; 1.2246x over previous
#include <cuda_runtime.h>
#include <cuda_bf16.h>
#include <stdint.h>

#define B_DIM 4
#define T_DIM 4096
#define C_DIM 1024
#define H_DIM 64
#define QTILE 128
#define KT64  64
#define GRID_W 296
#define NITEMS 576

// ---- device scratch (no cudaMalloc allowed) ----
__device__ __align__(16) __nv_bfloat16 g_wh[3 * C_DIM * H_DIM];
__device__ __align__(16) __nv_bfloat16 g_wl[3 * C_DIM * H_DIM];
__device__ __align__(16) __nv_bfloat16 g_Qh[B_DIM * T_DIM * H_DIM];
__device__ __align__(16) __nv_bfloat16 g_Ql[B_DIM * T_DIM * H_DIM];
__device__ __align__(16) __nv_bfloat16 g_Kh[B_DIM * T_DIM * H_DIM];
__device__ __align__(16) __nv_bfloat16 g_Kl[B_DIM * T_DIM * H_DIM];
__device__ __align__(16) __nv_bfloat16 g_VTh[B_DIM * H_DIM * T_DIM];  // [b][d][t]
__device__ __align__(16) __nv_bfloat16 g_VTl[B_DIM * H_DIM * T_DIM];
__device__ __align__(16) float  g_Op[8 * B_DIM * T_DIM * H_DIM];      // [p][b][t][d]
__device__ __align__(16) float2 g_ML[8 * B_DIM * T_DIM];              // [p][b][t]

#define Q_SCALE 0.04508422002778f   // 1/sqrt(1024) * log2(e)

__device__ __forceinline__ uint32_t smem_u32(const void* p) {
    uint32_t a;
    asm("{ .reg .u64 t; cvta.to.shared.u64 t, %1; cvt.u32.u64 %0, t; }"
        : "=r"(a) : "l"(p));
    return a;
}
__device__ __forceinline__ float ex2f(float x) {
    float y; asm("ex2.approx.ftz.f32 %0, %1;" : "=f"(y) : "f"(x)); return y;
}
__device__ __forceinline__ uint32_t pack_bf16(float a, float b) {
    __nv_bfloat162 t = __floats2bfloat162_rn(a, b);
    return *reinterpret_cast<uint32_t*>(&t);
}
__device__ __forceinline__ float bf_hi(float v) {
    return __bfloat162float(__float2bfloat16(v));
}
__device__ __forceinline__ void ldsm_x4(uint32_t& r0, uint32_t& r1,
                                        uint32_t& r2, uint32_t& r3, uint32_t a) {
    asm volatile("ldmatrix.sync.aligned.m8n8.x4.shared.b16 {%0,%1,%2,%3}, [%4];"
                 : "=r"(r0), "=r"(r1), "=r"(r2), "=r"(r3) : "r"(a));
}
__device__ __forceinline__ void ldsm_x4_t(uint32_t& r0, uint32_t& r1,
                                          uint32_t& r2, uint32_t& r3, uint32_t a) {
    asm volatile("ldmatrix.sync.aligned.m8n8.x4.trans.shared.b16 {%0,%1,%2,%3}, [%4];"
                 : "=r"(r0), "=r"(r1), "=r"(r2), "=r"(r3) : "r"(a));
}
__device__ __forceinline__ void mma16816(float* c, const uint32_t* a,
                                         uint32_t b0, uint32_t b1) {
    asm volatile("mma.sync.aligned.m16n8k16.row.col.f32.bf16.bf16.f32 "
                 "{%0,%1,%2,%3}, {%4,%5,%6,%7}, {%8,%9}, {%0,%1,%2,%3};"
                 : "+f"(c[0]), "+f"(c[1]), "+f"(c[2]), "+f"(c[3])
                 : "r"(a[0]), "r"(a[1]), "r"(a[2]), "r"(a[3]), "r"(b0), "r"(b1));
}
__device__ __forceinline__ void cpa16(uint32_t s, const void* g) {
    asm volatile("cp.async.cg.shared.global [%0], [%1], 16;" :: "r"(s), "l"(g) : "memory");
}
#define CP_COMMIT asm volatile("cp.async.commit_group;" ::: "memory")
#define CP_WAIT1  asm volatile("cp.async.wait_group 1;" ::: "memory")
#define CP_WAIT0  asm volatile("cp.async.wait_group 0;" ::: "memory")

// ---------------------------------------------------------------------------
// Split W (3 x 1024 x 64) into bf16 hi/lo. grid 192 x 256.
// ---------------------------------------------------------------------------
__global__ __launch_bounds__(256) void splitw_kernel(
    const float* __restrict__ Wq, const float* __restrict__ Wk,
    const float* __restrict__ Wv)
{
    int idx = blockIdx.x * 256 + threadIdx.x;
    int m = idx >> 14;
    int rem = idx & 16383;
    const float* W = (m == 0) ? Wq : (m == 1) ? Wk : Wv;
    float4 v = ((const float4*)W)[rem];
    float h0 = bf_hi(v.x), h1 = bf_hi(v.y), h2 = bf_hi(v.z), h3 = bf_hi(v.w);
    ((uint2*)g_wh)[idx] = make_uint2(pack_bf16(h0, h1), pack_bf16(h2, h3));
    ((uint2*)g_wl)[idx] = make_uint2(pack_bf16(v.x - h0, v.y - h1),
                                     pack_bf16(v.z - h2, v.w - h3));
}

// ---------------------------------------------------------------------------
// QKV projection: fp32 x staged via cp.async, split to bf16 in-kernel,
// mma.sync 3-pass split. Grid 128, block 256.
// ---------------------------------------------------------------------------
#define PXF 0
#define PXF_SZ (128 * 272)            // 34816 per stage (fp32 x, 272B stride)
#define PXH (2 * PXF_SZ)              // 69632 (bf16 hi, 144B stride)
#define PXL (PXH + 18432)             // 88064
#define PW  (PXL + 18432)             // 106496
#define PW_SZ 51200                   // per stage: WH 25600 + WL 25600
#define PSM_TOTAL (PW + 2 * PW_SZ)    // 208896

__global__ __launch_bounds__(256) void proj_kernel(const float* __restrict__ x)
{
    extern __shared__ char smem[];
    const uint32_t sb = smem_u32(smem);
    const int tid  = threadIdx.x;
    const int lane = tid & 31;
    const int w    = tid >> 5;
    const int gquad = lane >> 2;
    const int tql   = lane & 3;
    const int lr    = lane & 7;
    const uint32_t kofs = (uint32_t)(((lane >> 3) & 1) << 3);
    const uint32_t nofs = (uint32_t)((lane >> 4) << 3);

    const int row0 = blockIdx.x * 128;
    const float* xsrc = x + (size_t)row0 * C_DIM;

    auto load_stage = [&](int kc, int st) {
        uint32_t xf = sb + PXF + st * PXF_SZ;
#pragma unroll
        for (int it = 0; it < 8; it++) {
            int idx = tid + it * 256;          // 2048 float4
            int row = idx >> 4, seg = idx & 15;
            cpa16(xf + row * 272 + seg * 16, xsrc + (size_t)row * C_DIM + kc * 64 + seg * 4);
        }
        uint32_t wb = sb + PW + st * PW_SZ;
#pragma unroll
        for (int it = 0; it < 6; it++) {
            int idx = tid + it * 256;          // 1536
            int kr = idx / 24, s24 = idx - kr * 24;
            int m = s24 >> 3, seg = s24 & 7;
            size_t gsrc = ((size_t)m * C_DIM + kc * 64 + kr) * H_DIM + seg * 8;
            cpa16(wb + kr * 400 + s24 * 16, g_wh + gsrc);
            cpa16(wb + 25600 + kr * 400 + s24 * 16, g_wl + gsrc);
        }
    };

    load_stage(0, 0);
    CP_COMMIT;

    float s[24][4];
#pragma unroll
    for (int nb = 0; nb < 24; nb++)
#pragma unroll
        for (int e = 0; e < 4; e++) s[nb][e] = 0.f;

    const uint32_t a_row = 16 * w + (lane & 15);
    const uint32_t a_colb = (uint32_t)((lane >> 4) << 4);

    for (int kc = 0; kc < 16; kc++) {
        if (kc < 15) { load_stage(kc + 1, (kc + 1) & 1); CP_COMMIT; CP_WAIT1; }
        else         { CP_WAIT0; }
        __syncthreads();   // stage kc ready

        // convert fp32 x chunk -> split bf16 (single-buffered Xbf)
        {
            const char* xf = smem + PXF + (kc & 1) * PXF_SZ;
#pragma unroll
            for (int it = 0; it < 8; it++) {
                int idx = tid + it * 256;
                int row = idx >> 4, seg = idx & 15;
                float4 v = *(const float4*)(xf + row * 272 + seg * 16);
                float h0 = bf_hi(v.x), h1 = bf_hi(v.y), h2 = bf_hi(v.z), h3 = bf_hi(v.w);
                *(uint32_t*)(smem + PXH + row * 144 + seg * 8)     = pack_bf16(h0, h1);
                *(uint32_t*)(smem + PXH + row * 144 + seg * 8 + 4) = pack_bf16(h2, h3);
                *(uint32_t*)(smem + PXL + row * 144 + seg * 8)     = pack_bf16(v.x - h0, v.y - h1);
                *(uint32_t*)(smem + PXL + row * 144 + seg * 8 + 4) = pack_bf16(v.z - h2, v.w - h3);
            }
        }
        __syncthreads();   // Xbf visible

        const uint32_t wbase = sb + PW + (kc & 1) * PW_SZ;
#pragma unroll
        for (int ks = 0; ks < 4; ks++) {
            uint32_t ah[4], al[4];
            ldsm_x4(ah[0], ah[1], ah[2], ah[3], sb + PXH + a_row * 144 + ks * 32 + a_colb);
            ldsm_x4(al[0], al[1], al[2], al[3], sb + PXL + a_row * 144 + ks * 32 + a_colb);
            const uint32_t wrow = (uint32_t)(ks * 16) + kofs + lr;
#pragma unroll
            for (int np = 0; np < 12; np++) {
                uint32_t woff = wrow * 400 + (np * 16 + nofs) * 2;
                uint32_t h0, h1, h2, h3, l0, l1, l2, l3;
                ldsm_x4_t(h0, h1, h2, h3, wbase + woff);
                ldsm_x4_t(l0, l1, l2, l3, wbase + 25600 + woff);
                mma16816(s[2 * np], ah, h0, h1);
                mma16816(s[2 * np], ah, l0, l1);
                mma16816(s[2 * np], al, h0, h1);
                mma16816(s[2 * np + 1], ah, h2, h3);
                mma16816(s[2 * np + 1], ah, l2, l3);
                mma16816(s[2 * np + 1], al, h2, h3);
            }
        }
        // RACE FIX (round 12 bug): next iteration's load_stage overwrites the
        // same-parity W/XF buffers that lagging warps may still be reading in
        // this compute phase. Barrier before anyone issues the next cp.async.
        __syncthreads();
    }

    // ---- epilogue ----
    const int ra = 16 * w + gquad;
    const int rb = ra + 8;
    const size_t ga = (size_t)(row0 + ra) * H_DIM;
    const size_t gb = (size_t)(row0 + rb) * H_DIM;

#pragma unroll
    for (int nb = 0; nb < 8; nb++) {   // Q (scaled)
        int col = 8 * nb + 2 * tql;
        float q0 = s[nb][0] * Q_SCALE, q1 = s[nb][1] * Q_SCALE;
        float q2 = s[nb][2] * Q_SCALE, q3 = s[nb][3] * Q_SCALE;
        float h0 = bf_hi(q0), h1 = bf_hi(q1), h2 = bf_hi(q2), h3 = bf_hi(q3);
        *(uint32_t*)&g_Qh[ga + col] = pack_bf16(h0, h1);
        *(uint32_t*)&g_Ql[ga + col] = pack_bf16(q0 - h0, q1 - h1);
        *(uint32_t*)&g_Qh[gb + col] = pack_bf16(h2, h3);
        *(uint32_t*)&g_Ql[gb + col] = pack_bf16(q2 - h2, q3 - h3);
    }
#pragma unroll
    for (int nb = 8; nb < 16; nb++) {  // K
        int col = 8 * (nb - 8) + 2 * tql;
        float k0 = s[nb][0], k1 = s[nb][1], k2 = s[nb][2], k3 = s[nb][3];
        float h0 = bf_hi(k0), h1 = bf_hi(k1), h2 = bf_hi(k2), h3 = bf_hi(k3);
        *(uint32_t*)&g_Kh[ga + col] = pack_bf16(h0, h1);
        *(uint32_t*)&g_Kl[ga + col] = pack_bf16(k0 - h0, k1 - h1);
        *(uint32_t*)&g_Kh[gb + col] = pack_bf16(h2, h3);
        *(uint32_t*)&g_Kl[gb + col] = pack_bf16(k2 - h2, k3 - h3);
    }
    // V transposed staging in the (now free) XF region.
    char* VSH = smem;              // 64 x 272B
    char* VSL = smem + 17408;
#pragma unroll
    for (int nb = 16; nb < 24; nb++) {
        int d0 = 8 * (nb - 16) + 2 * tql;
        float v0 = s[nb][0], v1 = s[nb][1], v2 = s[nb][2], v3 = s[nb][3];
        float h0 = bf_hi(v0), h1 = bf_hi(v1), h2 = bf_hi(v2), h3 = bf_hi(v3);
        *(__nv_bfloat16*)(VSH + d0 * 272 + ra * 2)       = __float2bfloat16(h0);
        *(__nv_bfloat16*)(VSH + (d0 + 1) * 272 + ra * 2) = __float2bfloat16(h1);
        *(__nv_bfloat16*)(VSH + d0 * 272 + rb * 2)       = __float2bfloat16(h2);
        *(__nv_bfloat16*)(VSH + (d0 + 1) * 272 + rb * 2) = __float2bfloat16(h3);
        *(__nv_bfloat16*)(VSL + d0 * 272 + ra * 2)       = __float2bfloat16(v0 - h0);
        *(__nv_bfloat16*)(VSL + (d0 + 1) * 272 + ra * 2) = __float2bfloat16(v1 - h1);
        *(__nv_bfloat16*)(VSL + d0 * 272 + rb * 2)       = __float2bfloat16(v2 - h2);
        *(__nv_bfloat16*)(VSL + (d0 + 1) * 272 + rb * 2) = __float2bfloat16(v3 - h3);
    }
    __syncthreads();
    const int bI = row0 >> 12;
    const int t0 = row0 & (T_DIM - 1);
#pragma unroll
    for (int it = 0; it < 4; it++) {
        int idx = tid + it * 256;
        int d = idx >> 4, seg = idx & 15;
        size_t gdst = ((size_t)(bI * H_DIM + d)) * T_DIM + t0 + seg * 8;
        *(uint4*)&g_VTh[gdst] = *(uint4*)(VSH + d * 272 + seg * 16);
        *(uint4*)&g_VTl[gdst] = *(uint4*)(VSL + d * 272 + seg * 16);
    }
}

// ---------------------------------------------------------------------------
// Flash attention, KTILE=64, 2 CTAs/SM. Grid 296, block 256.
// 576 items (qt split into (qt>>2)+1 chunks), heavy-first.
// ---------------------------------------------------------------------------
#define SQH 0
#define SQL (SQH + 128 * 144)
#define KST0 (SQL + 128 * 144)          // 36864
#define STG_SZ 36864                    // kh 9216 | kl 9216 | vh 9216 | vl 9216
#define SM_TOTAL (KST0 + 2 * STG_SZ)    // 110592

__global__ __launch_bounds__(256, 2) void attn_kernel()
{
    extern __shared__ char smem[];
    const uint32_t sb = smem_u32(smem);
    const int tid  = threadIdx.x;
    const int lane = tid & 31;
    const int w    = tid >> 5;
    const int gquad = lane >> 2;
    const int tql   = lane & 3;
    const int lr    = lane & 7;
    const int lm    = lane >> 3;
    const uint32_t b_nboff = (uint32_t)(lm >> 1);
    const uint32_t b_kh    = (uint32_t)((lm & 1) << 4);
    const uint32_t a_row   = 16 * w + (lane & 15);
    const uint32_t a_colb  = (uint32_t)((lane >> 4) << 4);

    for (int item = blockIdx.x; item < NITEMS; item += GRID_W) {
        // ---- decode: groups g=7..0 (qt desc), count 16*(g+1) each ----
        int it2 = item, gg = 7;
        while (gg > 0) {
            int cnt = 16 * (gg + 1);
            if (it2 < cnt) break;
            it2 -= cnt; gg--;
        }
        const int npg  = gg + 1;
        const int qidx = it2 / (4 * npg);
        const int r    = it2 - qidx * 4 * npg;
        const int p    = r >> 2;
        const int b    = r & 3;
        const int qt   = 4 * gg + 3 - qidx;
        const int nkv  = 2 * qt + 2;               // total 64-tiles
        const int kt0  = p * nkv / npg;
        const int kt1  = (p + 1) * nkv / npg;
        const int q0   = qt * QTILE;

        const char* gqh = (const char*)(g_Qh + ((size_t)b * T_DIM + q0) * H_DIM);
        const char* gql = (const char*)(g_Ql + ((size_t)b * T_DIM + q0) * H_DIM);
        const char* gkh = (const char*)(g_Kh + (size_t)b * T_DIM * H_DIM);
        const char* gkl = (const char*)(g_Kl + (size_t)b * T_DIM * H_DIM);
        const char* gvh = (const char*)g_VTh + (size_t)b * H_DIM * T_DIM * 2;
        const char* gvl = (const char*)g_VTl + (size_t)b * H_DIM * T_DIM * 2;

        // ---- prologue: Q + first stage ----
#pragma unroll
        for (int it = 0; it < 4; it++) {
            int off = tid * 16 + it * 4096;
            int row = off >> 7, col = off & 127;
            cpa16(sb + SQH + row * 144 + col, gqh + off);
            cpa16(sb + SQL + row * 144 + col, gql + off);
        }
        {
            uint32_t st = sb + KST0;
#pragma unroll
            for (int it = 0; it < 2; it++) {
                int off = tid * 16 + it * 4096;
                int row = off >> 7, col = off & 127;
                cpa16(st + row * 144 + col, gkh + (size_t)kt0 * 8192 + off);
                cpa16(st + 9216 + row * 144 + col, gkl + (size_t)kt0 * 8192 + off);
                cpa16(st + 18432 + row * 144 + col,
                      gvh + (size_t)row * (T_DIM * 2) + kt0 * 128 + col);
                cpa16(st + 27648 + row * 144 + col,
                      gvl + (size_t)row * (T_DIM * 2) + kt0 * 128 + col);
            }
        }
        CP_COMMIT;

        float o[8][4];
#pragma unroll
        for (int d = 0; d < 8; d++)
#pragma unroll
            for (int e = 0; e < 4; e++) o[d][e] = 0.f;
        float m_a = -1e30f, m_b = -1e30f, l_a = 0.f, l_b = 0.f;

        const int row_a = q0 + 16 * w + gquad;
        const int row_b = row_a + 8;

        for (int kt = kt0; kt < kt1; kt++) {
            const int kv0 = kt * KT64;
            if (kt + 1 < kt1) {
                uint32_t st = sb + KST0 + ((kt + 1 - kt0) & 1) * STG_SZ;
                const size_t ko = (size_t)(kt + 1) * 8192;
                const int vo = (kt + 1) * 128;
#pragma unroll
                for (int it = 0; it < 2; it++) {
                    int off = tid * 16 + it * 4096;
                    int row = off >> 7, col = off & 127;
                    cpa16(st + row * 144 + col, gkh + ko + off);
                    cpa16(st + 9216 + row * 144 + col, gkl + ko + off);
                    cpa16(st + 18432 + row * 144 + col,
                          gvh + (size_t)row * (T_DIM * 2) + vo + col);
                    cpa16(st + 27648 + row * 144 + col,
                          gvl + (size_t)row * (T_DIM * 2) + vo + col);
                }
                CP_COMMIT;
                CP_WAIT1;
            } else {
                CP_WAIT0;
            }
            __syncthreads();

            const uint32_t stg = sb + KST0 + ((kt - kt0) & 1) * STG_SZ;

            // ---- S = Qh Kh^T + Qh Kl^T + Ql Kh^T  (m16 x n64) ----
            float s[8][4];
#pragma unroll
            for (int nb = 0; nb < 8; nb++)
#pragma unroll
                for (int e = 0; e < 4; e++) s[nb][e] = 0.f;

#pragma unroll
            for (int ks = 0; ks < 4; ks++) {
                uint32_t ah[4], al[4];
                ldsm_x4(ah[0], ah[1], ah[2], ah[3], sb + SQH + a_row * 144 + ks * 32 + a_colb);
                ldsm_x4(al[0], al[1], al[2], al[3], sb + SQL + a_row * 144 + ks * 32 + a_colb);
#pragma unroll
                for (int nbp = 0; nbp < 4; nbp++) {
                    int nb = 2 * nbp;
                    uint32_t baddr = (8 * (nb + b_nboff) + lr) * 144 + ks * 32 + b_kh;
                    uint32_t h0, h1, h2, h3, l0, l1, l2, l3;
                    ldsm_x4(h0, h1, h2, h3, stg + baddr);
                    ldsm_x4(l0, l1, l2, l3, stg + 9216 + baddr);
                    mma16816(s[nb], ah, h0, h1);
                    mma16816(s[nb], ah, l0, l1);
                    mma16816(s[nb], al, h0, h1);
                    mma16816(s[nb + 1], ah, h2, h3);
                    mma16816(s[nb + 1], ah, l2, l3);
                    mma16816(s[nb + 1], al, h2, h3);
                }
            }

            if (kt >= 2 * qt) {   // masking only in last two 64-tiles
#pragma unroll
                for (int nb = 0; nb < 8; nb++) {
                    int colg = kv0 + 8 * nb + 2 * tql;
                    if (colg > row_a)     s[nb][0] = -1e30f;
                    if (colg + 1 > row_a) s[nb][1] = -1e30f;
                    if (colg > row_b)     s[nb][2] = -1e30f;
                    if (colg + 1 > row_b) s[nb][3] = -1e30f;
                }
            }

            // ---- online softmax (base-2) ----
            float mt_a = -1e30f, mt_b = -1e30f;
#pragma unroll
            for (int nb = 0; nb < 8; nb++) {
                mt_a = fmaxf(mt_a, fmaxf(s[nb][0], s[nb][1]));
                mt_b = fmaxf(mt_b, fmaxf(s[nb][2], s[nb][3]));
            }
            mt_a = fmaxf(mt_a, __shfl_xor_sync(0xffffffffu, mt_a, 1));
            mt_a = fmaxf(mt_a, __shfl_xor_sync(0xffffffffu, mt_a, 2));
            mt_b = fmaxf(mt_b, __shfl_xor_sync(0xffffffffu, mt_b, 1));
            mt_b = fmaxf(mt_b, __shfl_xor_sync(0xffffffffu, mt_b, 2));

            float mn_a = fmaxf(m_a, mt_a), mn_b = fmaxf(m_b, mt_b);
            float al_a = ex2f(m_a - mn_a), al_b = ex2f(m_b - mn_b);
            m_a = mn_a; m_b = mn_b;

            float sum_a = 0.f, sum_b = 0.f;
#pragma unroll
            for (int nb = 0; nb < 8; nb++) {
                s[nb][0] = ex2f(s[nb][0] - mn_a);
                s[nb][1] = ex2f(s[nb][1] - mn_a);
                s[nb][2] = ex2f(s[nb][2] - mn_b);
                s[nb][3] = ex2f(s[nb][3] - mn_b);
                sum_a += s[nb][0] + s[nb][1];
                sum_b += s[nb][2] + s[nb][3];
            }
            sum_a += __shfl_xor_sync(0xffffffffu, sum_a, 1);
            sum_a += __shfl_xor_sync(0xffffffffu, sum_a, 2);
            sum_b += __shfl_xor_sync(0xffffffffu, sum_b, 1);
            sum_b += __shfl_xor_sync(0xffffffffu, sum_b, 2);
            l_a = l_a * al_a + sum_a;
            l_b = l_b * al_b + sum_b;

#pragma unroll
            for (int d = 0; d < 8; d++) {
                o[d][0] *= al_a; o[d][1] *= al_a;
                o[d][2] *= al_b; o[d][3] *= al_b;
            }

            // ---- O += Ph Vh + Ph Vl + Pl Vh ----
#pragma unroll
            for (int j = 0; j < 4; j++) {
                uint32_t ph[4], pl[4];
                float p00 = s[2 * j][0],     p01 = s[2 * j][1];
                float p02 = s[2 * j][2],     p03 = s[2 * j][3];
                float p10 = s[2 * j + 1][0], p11 = s[2 * j + 1][1];
                float p12 = s[2 * j + 1][2], p13 = s[2 * j + 1][3];
                float h00 = bf_hi(p00), h01 = bf_hi(p01), h02 = bf_hi(p02), h03 = bf_hi(p03);
                float h10 = bf_hi(p10), h11 = bf_hi(p11), h12 = bf_hi(p12), h13 = bf_hi(p13);
                ph[0] = pack_bf16(h00, h01); ph[1] = pack_bf16(h02, h03);
                ph[2] = pack_bf16(h10, h11); ph[3] = pack_bf16(h12, h13);
                pl[0] = pack_bf16(p00 - h00, p01 - h01);
                pl[1] = pack_bf16(p02 - h02, p03 - h03);
                pl[2] = pack_bf16(p10 - h10, p11 - h11);
                pl[3] = pack_bf16(p12 - h12, p13 - h13);
#pragma unroll
                for (int dp = 0; dp < 4; dp++) {
                    int d = 2 * dp;
                    uint32_t vaddr = (8 * (d + b_nboff) + lr) * 144 + j * 32 + b_kh;
                    uint32_t h0, h1, h2, h3, l0, l1, l2, l3;
                    ldsm_x4(h0, h1, h2, h3, stg + 18432 + vaddr);
                    ldsm_x4(l0, l1, l2, l3, stg + 27648 + vaddr);
                    mma16816(o[d], ph, h0, h1);
                    mma16816(o[d], ph, l0, l1);
                    mma16816(o[d], pl, h0, h1);
                    mma16816(o[d + 1], ph, h2, h3);
                    mma16816(o[d + 1], ph, l2, l3);
                    mma16816(o[d + 1], pl, h2, h3);
                }
            }
            __syncthreads();
        }

        // ---- partial epilogue ----
        {
            float* Op = g_Op + (size_t)(p * B_DIM + b) * T_DIM * H_DIM;
            float2* MLp = g_ML + (size_t)(p * B_DIM + b) * T_DIM;
#pragma unroll
            for (int d = 0; d < 8; d++) {
                int col = 8 * d + 2 * tql;
                *(float2*)&Op[(size_t)row_a * H_DIM + col] = make_float2(o[d][0], o[d][1]);
                *(float2*)&Op[(size_t)row_b * H_DIM + col] = make_float2(o[d][2], o[d][3]);
            }
            if (tql == 0) {
                MLp[row_a] = make_float2(m_a, l_a);
                MLp[row_b] = make_float2(m_b, l_b);
            }
        }
    }
}

// ---------------------------------------------------------------------------
// Combine partials -> out. Grid 4096 x 256.
// ---------------------------------------------------------------------------
__global__ __launch_bounds__(256) void combine_kernel(float* __restrict__ out)
{
    int idx = blockIdx.x * 256 + threadIdx.x;
    int col = idx & 63;
    int pr  = idx >> 6;
    int b   = pr >> 12;
    int t   = pr & (T_DIM - 1);
    int qt  = t >> 7;
    int np  = (qt >> 2) + 1;

    float m = -1e30f;
    for (int p = 0; p < np; p++)
        m = fmaxf(m, g_ML[(size_t)(p * B_DIM + b) * T_DIM + t].x);
    float l = 0.f, ov = 0.f;
    for (int p = 0; p < np; p++) {
        float2 ml = g_ML[(size_t)(p * B_DIM + b) * T_DIM + t];
        float wgt = ex2f(ml.x - m);
        l += ml.y * wgt;
        ov += g_Op[((size_t)(p * B_DIM + b) * T_DIM + t) * H_DIM + col] * wgt;
    }
    out[((size_t)b * T_DIM + t) * H_DIM + col] = ov / l;
}

// ---------------------------------------------------------------------------
extern "C" void kernel_launch(void* const* d_in, const int* in_sizes, int n_in,
                              void* d_out, int out_size)
{
    (void)in_sizes; (void)n_in; (void)out_size;
    const float* x  = (const float*)d_in[0];
    const float* Wq = (const float*)d_in[1];
    const float* Wk = (const float*)d_in[2];
    const float* Wv = (const float*)d_in[3];
    float* out = (float*)d_out;

    splitw_kernel<<<192, 256>>>(Wq, Wk, Wv);

    cudaFuncSetAttribute(proj_kernel,
                         cudaFuncAttributeMaxDynamicSharedMemorySize, PSM_TOTAL);
    proj_kernel<<<128, 256, PSM_TOTAL>>>(x);

    cudaFuncSetAttribute(attn_kernel,
                         cudaFuncAttributeMaxDynamicSharedMemorySize, SM_TOTAL);
    attn_kernel<<<GRID_W, 256, SM_TOTAL>>>();

    combine_kernel<<<4096, 256>>>(out);
}